// round 11
// baseline (speedup 1.0000x reference)
#include <cuda_runtime.h>
#include <cuda_bf16.h>
#include <cstdint>

#define BATCH   8
#define NPTS    4096
#define CIN_PTS 64
#define NPOINT  1024
#define NCENT   (BATCH * NPOINT)   // 8192
#define FEAT_W  320
#define S_IN    76                 // input stride: 67 used + zero pad
#define NTH     512                // threads per MLP block

// ---------------- device scratch ----------------
__device__ float g_new_xyz[NCENT * 3];
__device__ int   g_idx0[NCENT * 16];
__device__ int   g_idx1[NCENT * 32];
__device__ int   g_idx2[NCENT * 128];

__host__ __device__ constexpr int cmax3i(int a, int b, int c) {
    return a > b ? (a > c ? a : c) : (b > c ? b : c);
}
__host__ __device__ constexpr int cmax2i(int a, int b) { return a > b ? a : b; }

// =====================================================================
// FPS: one block per batch, 256 threads x 16 register-resident points.
// =====================================================================
__global__ __launch_bounds__(256) void fps_kernel(const float* __restrict__ xyz,
                                                  float* __restrict__ out_newxyz)
{
    int b = blockIdx.x;
    extern __shared__ float sm[];
    float* sx = sm;
    float* sy = sm + NPTS;
    float* sz = sm + 2 * NPTS;
    __shared__ unsigned long long skey[3];

    const float* base = xyz + (size_t)b * NPTS * 3;
    float px[16], py[16], pz[16], pd[16];
    #pragma unroll
    for (int r = 0; r < 16; r++) {
        int p = threadIdx.x + r * 256;
        float x = base[p * 3 + 0];
        float y = base[p * 3 + 1];
        float z = base[p * 3 + 2];
        sx[p] = x; sy[p] = y; sz[p] = z;
        px[r] = x; py[r] = y; pz[r] = z;
        pd[r] = 1e10f;
    }
    if (threadIdx.x == 0) {
        skey[0] = 0xFFFFFFFFull;   // decodes to index 0
        skey[1] = 0ull;
        skey[2] = 0ull;
    }
    __syncthreads();

    int lane = threadIdx.x & 31;

    for (int it = 0; it < NPOINT; it++) {
        int cur = it % 3, nxt = (it + 1) % 3, rst = (it + 2) % 3;
        unsigned int low = (unsigned int)skey[cur];
        int far = (int)(0xFFFFFFFFu - low);

        if (threadIdx.x == 0) {
            float fx = sx[far], fy = sy[far], fz = sz[far];
            int row = b * NPOINT + it;
            out_newxyz[row * 3 + 0] = fx;
            out_newxyz[row * 3 + 1] = fy;
            out_newxyz[row * 3 + 2] = fz;
            g_new_xyz[row * 3 + 0] = fx;
            g_new_xyz[row * 3 + 1] = fy;
            g_new_xyz[row * 3 + 2] = fz;
            skey[rst] = 0ull;
        }
        float cx = sx[far], cy = sy[far], cz = sz[far];

        float bv = -1.0f;
        int   bi = 0;
        #pragma unroll
        for (int r = 0; r < 16; r++) {
            float dx = px[r] - cx;
            float dy = py[r] - cy;
            float dz = pz[r] - cz;
            float d = __fadd_rn(__fadd_rn(__fmul_rn(dx, dx), __fmul_rn(dy, dy)),
                                __fmul_rn(dz, dz));
            float nd = fminf(pd[r], d);
            pd[r] = nd;
            if (nd > bv) { bv = nd; bi = threadIdx.x + r * 256; }
        }
        #pragma unroll
        for (int off = 16; off >= 1; off >>= 1) {
            float ov = __shfl_down_sync(0xffffffffu, bv, off);
            int   oi = __shfl_down_sync(0xffffffffu, bi, off);
            if (ov > bv || (ov == bv && oi < bi)) { bv = ov; bi = oi; }
        }
        if (lane == 0) {
            unsigned long long key =
                ((unsigned long long)__float_as_uint(bv) << 32) |
                (unsigned long long)(0xFFFFFFFFu - (unsigned int)bi);
            atomicMax(&skey[nxt], key);
        }
        __syncthreads();
    }
}

// =====================================================================
// Fused ball query (3 radii, one smem-staged scan). Warp per center.
// =====================================================================
__global__ __launch_bounds__(256) void bq_fused_kernel(const float* __restrict__ xyz,
                                                       int* __restrict__ o0,
                                                       int* __restrict__ o1,
                                                       int* __restrict__ o2)
{
    extern __shared__ float sm[];
    float* sx = sm;
    float* sy = sm + NPTS;
    float* sz = sm + 2 * NPTS;

    int wid  = threadIdx.x >> 5;
    int lane = threadIdx.x & 31;
    int gw   = blockIdx.x * 8 + wid;
    int b    = gw >> 10;

    const float* base = xyz + (size_t)b * NPTS * 3;
    for (int t = threadIdx.x; t < NPTS * 3; t += 256) {
        int p = t / 3, c = t - p * 3;
        float v = base[t];
        (c == 0 ? sx : (c == 1 ? sy : sz))[p] = v;
    }
    __syncthreads();

    const float r2_0 = (float)(0.1 * 0.1);
    const float r2_1 = (float)(0.2 * 0.2);
    const float r2_2 = (float)(0.4 * 0.4);

    float cx = g_new_xyz[gw * 3 + 0];
    float cy = g_new_xyz[gw * 3 + 1];
    float cz = g_new_xyz[gw * 3 + 2];

    int* p0 = o0 + (size_t)gw * 16;
    int* p1 = o1 + (size_t)gw * 32;
    int* p2 = o2 + (size_t)gw * 128;

    int c0 = 0, c1 = 0, c2 = 0;
    int f0 = -1, f1 = -1, f2 = -1;
    unsigned lmask = (1u << lane) - 1u;

    for (int s = 0; s < NPTS; s += 32) {
        int p = s + lane;
        float dx = sx[p] - cx;
        float dy = sy[p] - cy;
        float dz = sz[p] - cz;
        float d2 = __fadd_rn(__fadd_rn(__fmul_rn(dx, dx), __fmul_rn(dy, dy)),
                             __fmul_rn(dz, dz));
        bool h0 = d2 < r2_0, h1 = d2 < r2_1, h2 = d2 < r2_2;
        unsigned m0 = __ballot_sync(0xffffffffu, h0);
        unsigned m1 = __ballot_sync(0xffffffffu, h1);
        unsigned m2 = __ballot_sync(0xffffffffu, h2);
        if (m0) {
            if (f0 < 0) f0 = s + (__ffs(m0) - 1);
            if (h0) { int pos = c0 + __popc(m0 & lmask); if (pos < 16) p0[pos] = p; }
            c0 += __popc(m0);
        }
        if (m1) {
            if (f1 < 0) f1 = s + (__ffs(m1) - 1);
            if (h1) { int pos = c1 + __popc(m1 & lmask); if (pos < 32) p1[pos] = p; }
            c1 += __popc(m1);
        }
        if (m2) {
            if (f2 < 0) f2 = s + (__ffs(m2) - 1);
            if (h2) { int pos = c2 + __popc(m2 & lmask); if (pos < 128) p2[pos] = p; }
            c2 += __popc(m2);
        }
        if (c0 >= 16 && c1 >= 32 && c2 >= 128) break;
    }
    for (int pos = c0 + lane; pos < 16; pos += 32) p0[pos] = f0;
    for (int pos = c1 + lane; pos < 32; pos += 32) p1[pos] = f1;
    for (int pos = c2 + lane; pos < 128; pos += 32) p2[pos] = f2;
}

// =====================================================================
// zero-init the scale-2 output region (needed for cross-block atomicMax)
// =====================================================================
__global__ __launch_bounds__(512) void zero_feat2_kernel(float* __restrict__ outF)
{
    int idx = blockIdx.x * 512 + threadIdx.x;   // < 8192*128
    int gid = idx >> 7, c = idx & 127;
    outF[(size_t)gid * FEAT_W + 192 + c] = 0.0f;
}

// =====================================================================
// tf32 mma building blocks. 512 threads: 4 m-warps (w>>2) x 4 n-warps (w&3).
// MT = 16-row m-tiles per warp (2 -> 128-row block, 1 -> 64-row block).
// =====================================================================
__device__ __forceinline__ uint32_t f2tf32(float f) {
    uint32_t r; asm("cvt.rna.tf32.f32 %0, %1;" : "=r"(r) : "f"(f)); return r;
}

__device__ __forceinline__ void mma_tf32(float* d, const uint32_t* a, const uint32_t* b) {
    asm volatile("mma.sync.aligned.m16n8k8.row.col.f32.tf32.tf32.f32 "
                 "{%0,%1,%2,%3},{%4,%5,%6,%7},{%8,%9},{%0,%1,%2,%3};"
                 : "+f"(d[0]), "+f"(d[1]), "+f"(d[2]), "+f"(d[3])
                 : "r"(a[0]), "r"(a[1]), "r"(a[2]), "r"(a[3]),
                   "r"(b[0]), "r"(b[1]));
}

template<int KSTEPS, int SA, int NP, int NT, int MT>
__device__ __forceinline__ void mma_accum(const float* __restrict__ sA, int kOff,
                                          const float* __restrict__ sW,
                                          float (&acc)[MT][NT][4])
{
    int lane = threadIdx.x & 31;
    int w    = threadIdx.x >> 5;
    int g    = lane >> 2;
    int tg   = lane & 3;
    int m0   = (w >> 2) * (16 * MT);
    int n0   = (w & 3) * (NT * 8);

    for (int ks = 0; ks < KSTEPS; ks++) {
        int k0 = ks * 8;
        uint32_t a[MT][4];
        #pragma unroll
        for (int mt = 0; mt < MT; mt++) {
            const float* Ab = sA + (m0 + 16 * mt) * SA + kOff + k0;
            a[mt][0] = f2tf32(Ab[g * SA + tg]);
            a[mt][1] = f2tf32(Ab[(g + 8) * SA + tg]);
            a[mt][2] = f2tf32(Ab[g * SA + tg + 4]);
            a[mt][3] = f2tf32(Ab[(g + 8) * SA + tg + 4]);
        }
        #pragma unroll
        for (int nt = 0; nt < NT; nt++) {
            const float* Wb = sW + k0 * NP + n0 + 8 * nt;
            uint32_t bfr[2];
            bfr[0] = f2tf32(Wb[tg * NP + g]);
            bfr[1] = f2tf32(Wb[(tg + 4) * NP + g]);
            #pragma unroll
            for (int mt = 0; mt < MT; mt++)
                mma_tf32(acc[mt][nt], a[mt], bfr);
        }
    }
}

template<int NT, int SOUT, int MT>
__device__ __forceinline__ void epi_relu(float (&acc)[MT][NT][4],
                                         const float* __restrict__ gBias,
                                         float* __restrict__ sOut)
{
    int lane = threadIdx.x & 31;
    int w    = threadIdx.x >> 5;
    int g    = lane >> 2;
    int tg   = lane & 3;
    int m0   = (w >> 2) * (16 * MT);
    int n0   = (w & 3) * (NT * 8);
    #pragma unroll
    for (int mt = 0; mt < MT; mt++)
        #pragma unroll
        for (int nt = 0; nt < NT; nt++) {
            int row = m0 + 16 * mt + g;
            int col = n0 + 8 * nt + 2 * tg;
            float b0v = gBias[col], b1v = gBias[col + 1];
            sOut[row * SOUT + col]           = fmaxf(acc[mt][nt][0] + b0v, 0.0f);
            sOut[row * SOUT + col + 1]       = fmaxf(acc[mt][nt][1] + b1v, 0.0f);
            sOut[(row + 8) * SOUT + col]     = fmaxf(acc[mt][nt][2] + b0v, 0.0f);
            sOut[(row + 8) * SOUT + col + 1] = fmaxf(acc[mt][nt][3] + b1v, 0.0f);
        }
}

template<int NT, int SEG, int MT>
__device__ __forceinline__ void epi_final(float (&acc)[MT][NT][4],
                                          const float* __restrict__ gBias,
                                          int* __restrict__ sMaxI,
                                          float* __restrict__ outF, int centerBase)
{
    int lane = threadIdx.x & 31;
    int w    = threadIdx.x >> 5;
    int g    = lane >> 2;
    int tg   = lane & 3;
    int n0   = (w & 3) * (NT * 8);

    if (SEG == 128) {
        // all m-warps cover (part of) one center: shared atomicMax combine
        #pragma unroll
        for (int nt = 0; nt < NT; nt++) {
            int col = n0 + 8 * nt + 2 * tg;
            float v0, v1;
            if (MT == 2) {
                v0 = fmaxf(fmaxf(acc[0][nt][0], acc[0][nt][2]),
                           fmaxf(acc[1 % MT][nt][0], acc[1 % MT][nt][2]));
                v1 = fmaxf(fmaxf(acc[0][nt][1], acc[0][nt][3]),
                           fmaxf(acc[1 % MT][nt][1], acc[1 % MT][nt][3]));
            } else {
                v0 = fmaxf(acc[0][nt][0], acc[0][nt][2]);
                v1 = fmaxf(acc[0][nt][1], acc[0][nt][3]);
            }
            v0 = fmaxf(v0 + gBias[col], 0.0f);
            v1 = fmaxf(v1 + gBias[col + 1], 0.0f);
            #pragma unroll
            for (int off = 4; off < 32; off <<= 1) {
                v0 = fmaxf(v0, __shfl_xor_sync(0xffffffffu, v0, off));
                v1 = fmaxf(v1, __shfl_xor_sync(0xffffffffu, v1, off));
            }
            if (g == 0) {
                atomicMax(&sMaxI[col],     __float_as_int(v0));
                atomicMax(&sMaxI[col + 1], __float_as_int(v1));
            }
        }
    } else if (SEG == 32) {   // MT == 2 only
        int center = centerBase + (w >> 2);
        #pragma unroll
        for (int nt = 0; nt < NT; nt++) {
            int col = n0 + 8 * nt + 2 * tg;
            float v0 = fmaxf(fmaxf(acc[0][nt][0], acc[0][nt][2]),
                             fmaxf(acc[1 % MT][nt][0], acc[1 % MT][nt][2]));
            float v1 = fmaxf(fmaxf(acc[0][nt][1], acc[0][nt][3]),
                             fmaxf(acc[1 % MT][nt][1], acc[1 % MT][nt][3]));
            #pragma unroll
            for (int off = 4; off < 32; off <<= 1) {
                v0 = fmaxf(v0, __shfl_xor_sync(0xffffffffu, v0, off));
                v1 = fmaxf(v1, __shfl_xor_sync(0xffffffffu, v1, off));
            }
            if (g == 0) {
                float* op = outF + (size_t)center * FEAT_W;
                op[col]     = fmaxf(v0 + gBias[col], 0.0f);
                op[col + 1] = fmaxf(v1 + gBias[col + 1], 0.0f);
            }
        }
    } else {                  // SEG == 16, MT == 2 only
        #pragma unroll
        for (int mt = 0; mt < MT; mt++) {
            int center = centerBase + (w >> 2) * 2 + mt;
            #pragma unroll
            for (int nt = 0; nt < NT; nt++) {
                int col = n0 + 8 * nt + 2 * tg;
                float v0 = fmaxf(acc[mt][nt][0], acc[mt][nt][2]);
                float v1 = fmaxf(acc[mt][nt][1], acc[mt][nt][3]);
                #pragma unroll
                for (int off = 4; off < 32; off <<= 1) {
                    v0 = fmaxf(v0, __shfl_xor_sync(0xffffffffu, v0, off));
                    v1 = fmaxf(v1, __shfl_xor_sync(0xffffffffu, v1, off));
                }
                if (g == 0) {
                    float* op = outF + (size_t)center * FEAT_W;
                    op[col]     = fmaxf(v0 + gBias[col], 0.0f);
                    op[col + 1] = fmaxf(v1 + gBias[col + 1], 0.0f);
                }
            }
        }
    }
}

template<int ROWS, int KR, int NC, int NP>
__device__ __forceinline__ void stage_w(float* __restrict__ sW, const float* __restrict__ gW)
{
    for (int t = threadIdx.x; t < ROWS * NP; t += NTH) {
        int r = t / NP, c = t - r * NP;
        sW[t] = (r < KR && c < NC) ? gW[r * NC + c] : 0.0f;
    }
}

// =====================================================================
// Unified MLP kernel. MT=2: 128-row block (as round 6). MT=1: 64-row
// block = half a SEG=128 center; cross-block maxpool via global atomicMax.
// =====================================================================
template<int SEG, int C1, int C2, int C3, int MT, int MINB>
__global__ __launch_bounds__(NTH, MINB) void mlp_mma_kernel(
    const float* __restrict__ xyz,
    const float* __restrict__ points,
    const int* __restrict__ idxbuf,
    const float* __restrict__ W1, const float* __restrict__ B1,
    const float* __restrict__ W2, const float* __restrict__ B2,
    const float* __restrict__ W3, const float* __restrict__ B3,
    float* __restrict__ outF)
{
    constexpr int ROWS = 64 * MT;
    constexpr int CPB  = ROWS / SEG > 0 ? ROWS / SEG : 1;
    constexpr int S1   = C1 + 4, S2 = C2 + 4;
    constexpr int NP1  = C1 + 8, NP2 = C2 + 8, NP3 = C3 + 8;
    constexpr int W3CH = (C2 == 96) ? 48 : C2;   // W3 staging chunk rows
    constexpr int NCH  = C2 / W3CH;
    constexpr int REG0 = ROWS * cmax2i(S_IN, S2);
    constexpr int WMAX = cmax3i(72 * NP1, C1 * NP2, W3CH * NP3);
    constexpr int KS2  = C1 / 8;
    constexpr int NT1  = C1 / 32, NT2 = C2 / 32, NT3 = C3 / 32;

    extern __shared__ float sm[];
    float* sIn   = sm;                  // [REG0] (later reused as buf2)
    float* buf1  = sm + REG0;           // ROWS * S1
    float* sW    = buf1 + ROWS * S1;    // WMAX
    int*   sMaxI = (int*)(sW + WMAX);   // 128
    int*   sIdx  = sMaxI + 128;         // 128

    int centerBase, rowOff;
    if (SEG == 128 && MT == 1) {
        centerBase = blockIdx.x >> 1;
        rowOff     = (blockIdx.x & 1) * 64;
    } else {
        centerBase = blockIdx.x * CPB;
        rowOff     = 0;
    }
    int b = centerBase >> 10;

    for (int t = threadIdx.x; t < 128; t += NTH) sMaxI[t] = 0;
    for (int t = threadIdx.x; t < ROWS; t += NTH)
        sIdx[t] = idxbuf[(size_t)centerBase * SEG + rowOff + t];
    __syncthreads();

    const float* pB = points + (size_t)b * NPTS * CIN_PTS;
    const float* xB = xyz + (size_t)b * NPTS * 3;

    for (int t = threadIdx.x; t < ROWS * S_IN; t += NTH) {
        int s = t / S_IN, c = t - s * S_IN;
        int ci = centerBase + (rowOff + s) / SEG;
        float v;
        if (c < 64)       v = pB[(size_t)sIdx[s] * CIN_PTS + c];
        else if (c < 67) {
            int d = c - 64;
            v = xB[(size_t)sIdx[s] * 3 + d] - g_new_xyz[ci * 3 + d];
        } else v = 0.0f;
        sIn[t] = v;
    }
    stage_w<72, 67, C1, NP1>(sW, W1);
    __syncthreads();

    // layer 1: sIn -> buf1
    {
        float acc[MT][NT1][4];
        #pragma unroll
        for (int mt = 0; mt < MT; mt++)
            #pragma unroll
            for (int nt = 0; nt < NT1; nt++)
                #pragma unroll
                for (int i = 0; i < 4; i++) acc[mt][nt][i] = 0.0f;
        mma_accum<9, S_IN, NP1, NT1, MT>(sIn, 0, sW, acc);
        epi_relu<NT1, S1, MT>(acc, B1, buf1);
    }
    __syncthreads();

    stage_w<C1, C1, C2, NP2>(sW, W2);
    __syncthreads();

    // layer 2: buf1 -> buf2 (aliases sIn)
    float* buf2 = sIn;
    {
        float acc[MT][NT2][4];
        #pragma unroll
        for (int mt = 0; mt < MT; mt++)
            #pragma unroll
            for (int nt = 0; nt < NT2; nt++)
                #pragma unroll
                for (int i = 0; i < 4; i++) acc[mt][nt][i] = 0.0f;
        mma_accum<KS2, S1, NP2, NT2, MT>(buf1, 0, sW, acc);
        epi_relu<NT2, S2, MT>(acc, B2, buf2);
    }
    __syncthreads();

    // layer 3: buf2 -> maxpool. W3 [C2][C3] staged in NCH chunks.
    {
        float acc[MT][NT3][4];
        #pragma unroll
        for (int mt = 0; mt < MT; mt++)
            #pragma unroll
            for (int nt = 0; nt < NT3; nt++)
                #pragma unroll
                for (int i = 0; i < 4; i++) acc[mt][nt][i] = 0.0f;
        for (int ch = 0; ch < NCH; ch++) {
            stage_w<W3CH, W3CH, C3, NP3>(sW, W3 + (size_t)ch * W3CH * C3);
            __syncthreads();
            mma_accum<W3CH / 8, S2, NP3, NT3, MT>(buf2, ch * W3CH, sW, acc);
            __syncthreads();
        }
        epi_final<NT3, SEG, MT>(acc, B3, sMaxI, outF, centerBase);
    }

    if (SEG == 128) {
        __syncthreads();
        if (MT == 2) {
            for (int t = threadIdx.x; t < C3; t += NTH)
                outF[(size_t)centerBase * FEAT_W + t] = __int_as_float(sMaxI[t]);
        } else {
            for (int t = threadIdx.x; t < C3; t += NTH)
                atomicMax((int*)(outF + (size_t)centerBase * FEAT_W + t), sMaxI[t]);
        }
    }
}

// =====================================================================
// host launch
// =====================================================================
template<int SEG, int C1, int C2, int C3, int MT>
static constexpr int smem_mma() {
    constexpr int ROWS = 64 * MT;
    constexpr int S2 = C2 + 4;
    constexpr int W3CH = (C2 == 96) ? 48 : C2;
    constexpr int WMAX = cmax3i(72 * (C1 + 8), C1 * (C2 + 8), W3CH * (C3 + 8));
    constexpr int REG0 = ROWS * cmax2i(S_IN, S2);
    return (REG0 + ROWS * (C1 + 4) + WMAX + 256) * 4;
}

extern "C" void kernel_launch(void* const* d_in, const int* in_sizes, int n_in,
                              void* d_out, int out_size)
{
    const float* xyz = (const float*)d_in[0];
    const float* pts = (const float*)d_in[1];
    const float* W[3][3];
    const float* Bv[3][3];
    int k = 2;
    for (int bi = 0; bi < 3; bi++)
        for (int li = 0; li < 3; li++) {
            W[bi][li]  = (const float*)d_in[k++];
            Bv[bi][li] = (const float*)d_in[k++];
        }

    float* out        = (float*)d_out;
    float* out_newxyz = out;
    float* out_feat   = out + (size_t)NCENT * 3;

    const int fps_smem = 3 * NPTS * 4;
    const int bq_smem  = 3 * NPTS * 4;
    constexpr int sm0 = smem_mma<16, 32, 32, 64, 2>();     //  69,888 B
    constexpr int sm1 = smem_mma<32, 64, 64, 128, 2>();    // 109,568 B -> 2/SM
    constexpr int sm2 = smem_mma<128, 64, 96, 128, 1>();   //  70,656 B -> 3/SM

    cudaFuncSetAttribute(fps_kernel, cudaFuncAttributeMaxDynamicSharedMemorySize, fps_smem);
    cudaFuncSetAttribute((const void*)mlp_mma_kernel<16, 32, 32, 64, 2, 2>,
                         cudaFuncAttributeMaxDynamicSharedMemorySize, sm0);
    cudaFuncSetAttribute((const void*)mlp_mma_kernel<32, 64, 64, 128, 2, 2>,
                         cudaFuncAttributeMaxDynamicSharedMemorySize, sm1);
    cudaFuncSetAttribute((const void*)mlp_mma_kernel<128, 64, 96, 128, 1, 3>,
                         cudaFuncAttributeMaxDynamicSharedMemorySize, sm2);

    zero_feat2_kernel<<<NCENT * 128 / 512, 512>>>(out_feat);
    fps_kernel<<<BATCH, 256, fps_smem>>>(xyz, out_newxyz);
    bq_fused_kernel<<<NCENT / 8, 256, bq_smem>>>(xyz, g_idx0, g_idx1, g_idx2);

    mlp_mma_kernel<128, 64, 96, 128, 1, 3><<<NCENT * 2, NTH, sm2>>>(
        xyz, pts, g_idx2,
        W[2][0], Bv[2][0], W[2][1], Bv[2][1], W[2][2], Bv[2][2],
        out_feat + 192);
    mlp_mma_kernel<32, 64, 64, 128, 2, 2><<<NCENT / 4, NTH, sm1>>>(
        xyz, pts, g_idx1,
        W[1][0], Bv[1][0], W[1][1], Bv[1][1], W[1][2], Bv[1][2],
        out_feat + 64);
    mlp_mma_kernel<16, 32, 32, 64, 2, 2><<<NCENT / 8, NTH, sm0>>>(
        xyz, pts, g_idx0,
        W[0][0], Bv[0][0], W[0][1], Bv[0][1], W[0][2], Bv[0][2],
        out_feat + 0);
}

// round 12
// speedup vs baseline: 1.2684x; 1.2684x over previous
#include <cuda_runtime.h>
#include <cuda_fp16.h>
#include <cstdint>

#define BATCH   8
#define NPTS    4096
#define CIN_PTS 64
#define NPOINT  1024
#define NCENT   (BATCH * NPOINT)   // 8192
#define FEAT_W  320
#define NTH     512                // threads per MLP block
#define SH_IN   88                 // sIn stride in halves (covers k reads to 79)

// ---------------- device scratch ----------------
__device__ float g_new_xyz[NCENT * 3];
__device__ int   g_idx0[NCENT * 16];
__device__ int   g_idx1[NCENT * 32];
__device__ int   g_idx2[NCENT * 128];

__host__ __device__ constexpr int cmax3i(int a, int b, int c) {
    return a > b ? (a > c ? a : c) : (b > c ? b : c);
}
__host__ __device__ constexpr int cmax2i(int a, int b) { return a > b ? a : b; }
// pad (in halves) so word-stride mod 32 in {4,12,20,28} -> conflict-free frag loads
__host__ __device__ constexpr int SHPAD(int k) {
    int m = (k + 7) & ~7;
    while (!((m % 64 == 8) || (m % 64 == 24) || (m % 64 == 40) || (m % 64 == 56))) m += 8;
    return m;
}

// =====================================================================
// FPS: one block per batch, 256 threads x 16 register-resident points.
// =====================================================================
__global__ __launch_bounds__(256) void fps_kernel(const float* __restrict__ xyz,
                                                  float* __restrict__ out_newxyz)
{
    int b = blockIdx.x;
    extern __shared__ float sm[];
    float* sx = sm;
    float* sy = sm + NPTS;
    float* sz = sm + 2 * NPTS;
    __shared__ unsigned long long skey[3];

    const float* base = xyz + (size_t)b * NPTS * 3;
    float px[16], py[16], pz[16], pd[16];
    #pragma unroll
    for (int r = 0; r < 16; r++) {
        int p = threadIdx.x + r * 256;
        float x = base[p * 3 + 0];
        float y = base[p * 3 + 1];
        float z = base[p * 3 + 2];
        sx[p] = x; sy[p] = y; sz[p] = z;
        px[r] = x; py[r] = y; pz[r] = z;
        pd[r] = 1e10f;
    }
    if (threadIdx.x == 0) {
        skey[0] = 0xFFFFFFFFull;   // decodes to index 0
        skey[1] = 0ull;
        skey[2] = 0ull;
    }
    __syncthreads();

    int lane = threadIdx.x & 31;

    for (int it = 0; it < NPOINT; it++) {
        int cur = it % 3, nxt = (it + 1) % 3, rst = (it + 2) % 3;
        unsigned int low = (unsigned int)skey[cur];
        int far = (int)(0xFFFFFFFFu - low);

        if (threadIdx.x == 0) {
            float fx = sx[far], fy = sy[far], fz = sz[far];
            int row = b * NPOINT + it;
            out_newxyz[row * 3 + 0] = fx;
            out_newxyz[row * 3 + 1] = fy;
            out_newxyz[row * 3 + 2] = fz;
            g_new_xyz[row * 3 + 0] = fx;
            g_new_xyz[row * 3 + 1] = fy;
            g_new_xyz[row * 3 + 2] = fz;
            skey[rst] = 0ull;
        }
        float cx = sx[far], cy = sy[far], cz = sz[far];

        float bv = -1.0f;
        int   bi = 0;
        #pragma unroll
        for (int r = 0; r < 16; r++) {
            float dx = px[r] - cx;
            float dy = py[r] - cy;
            float dz = pz[r] - cz;
            float d = __fadd_rn(__fadd_rn(__fmul_rn(dx, dx), __fmul_rn(dy, dy)),
                                __fmul_rn(dz, dz));
            float nd = fminf(pd[r], d);
            pd[r] = nd;
            if (nd > bv) { bv = nd; bi = threadIdx.x + r * 256; }
        }
        #pragma unroll
        for (int off = 16; off >= 1; off >>= 1) {
            float ov = __shfl_down_sync(0xffffffffu, bv, off);
            int   oi = __shfl_down_sync(0xffffffffu, bi, off);
            if (ov > bv || (ov == bv && oi < bi)) { bv = ov; bi = oi; }
        }
        if (lane == 0) {
            unsigned long long key =
                ((unsigned long long)__float_as_uint(bv) << 32) |
                (unsigned long long)(0xFFFFFFFFu - (unsigned int)bi);
            atomicMax(&skey[nxt], key);
        }
        __syncthreads();
    }
}

// =====================================================================
// Fused ball query (3 radii, one smem-staged scan). Warp per center.
// =====================================================================
__global__ __launch_bounds__(256) void bq_fused_kernel(const float* __restrict__ xyz,
                                                       int* __restrict__ o0,
                                                       int* __restrict__ o1,
                                                       int* __restrict__ o2)
{
    extern __shared__ float sm[];
    float* sx = sm;
    float* sy = sm + NPTS;
    float* sz = sm + 2 * NPTS;

    int wid  = threadIdx.x >> 5;
    int lane = threadIdx.x & 31;
    int gw   = blockIdx.x * 8 + wid;
    int b    = gw >> 10;

    const float* base = xyz + (size_t)b * NPTS * 3;
    for (int t = threadIdx.x; t < NPTS * 3; t += 256) {
        int p = t / 3, c = t - p * 3;
        float v = base[t];
        (c == 0 ? sx : (c == 1 ? sy : sz))[p] = v;
    }
    __syncthreads();

    const float r2_0 = (float)(0.1 * 0.1);
    const float r2_1 = (float)(0.2 * 0.2);
    const float r2_2 = (float)(0.4 * 0.4);

    float cx = g_new_xyz[gw * 3 + 0];
    float cy = g_new_xyz[gw * 3 + 1];
    float cz = g_new_xyz[gw * 3 + 2];

    int* p0 = o0 + (size_t)gw * 16;
    int* p1 = o1 + (size_t)gw * 32;
    int* p2 = o2 + (size_t)gw * 128;

    int c0 = 0, c1 = 0, c2 = 0;
    int f0 = -1, f1 = -1, f2 = -1;
    unsigned lmask = (1u << lane) - 1u;

    for (int s = 0; s < NPTS; s += 32) {
        int p = s + lane;
        float dx = sx[p] - cx;
        float dy = sy[p] - cy;
        float dz = sz[p] - cz;
        float d2 = __fadd_rn(__fadd_rn(__fmul_rn(dx, dx), __fmul_rn(dy, dy)),
                             __fmul_rn(dz, dz));
        bool h0 = d2 < r2_0, h1 = d2 < r2_1, h2 = d2 < r2_2;
        unsigned m0 = __ballot_sync(0xffffffffu, h0);
        unsigned m1 = __ballot_sync(0xffffffffu, h1);
        unsigned m2 = __ballot_sync(0xffffffffu, h2);
        if (m0) {
            if (f0 < 0) f0 = s + (__ffs(m0) - 1);
            if (h0) { int pos = c0 + __popc(m0 & lmask); if (pos < 16) p0[pos] = p; }
            c0 += __popc(m0);
        }
        if (m1) {
            if (f1 < 0) f1 = s + (__ffs(m1) - 1);
            if (h1) { int pos = c1 + __popc(m1 & lmask); if (pos < 32) p1[pos] = p; }
            c1 += __popc(m1);
        }
        if (m2) {
            if (f2 < 0) f2 = s + (__ffs(m2) - 1);
            if (h2) { int pos = c2 + __popc(m2 & lmask); if (pos < 128) p2[pos] = p; }
            c2 += __popc(m2);
        }
        if (c0 >= 16 && c1 >= 32 && c2 >= 128) break;
    }
    for (int pos = c0 + lane; pos < 16; pos += 32) p0[pos] = f0;
    for (int pos = c1 + lane; pos < 32; pos += 32) p1[pos] = f1;
    for (int pos = c2 + lane; pos < 128; pos += 32) p2[pos] = f2;
}

// =====================================================================
// fp16 m16n8k16 mma pipeline. 512 threads: 4 m-warps x 4 n-warps.
// Activations + weights in smem as fp16 (no cvt in mainloop).
// W stored TRANSPOSED [N][KH] so B fragments are 2x LDS.32.
// =====================================================================
__device__ __forceinline__ void mma_f16(float* d, const uint32_t* a, const uint32_t* b) {
    asm volatile("mma.sync.aligned.m16n8k16.row.col.f32.f16.f16.f32 "
                 "{%0,%1,%2,%3},{%4,%5,%6,%7},{%8,%9},{%0,%1,%2,%3};"
                 : "+f"(d[0]), "+f"(d[1]), "+f"(d[2]), "+f"(d[3])
                 : "r"(a[0]), "r"(a[1]), "r"(a[2]), "r"(a[3]),
                   "r"(b[0]), "r"(b[1]));
}

// A: [128][SA] halves; W: [N][KH] halves (transposed). KSTEPS k16-steps.
template<int KSTEPS, int SA, int KH, int NT>
__device__ __forceinline__ void mma_accum(const __half* __restrict__ sA, int kOff,
                                          const __half* __restrict__ sW,
                                          float (&acc)[2][NT][4])
{
    int lane = threadIdx.x & 31;
    int w    = threadIdx.x >> 5;
    int g    = lane >> 2;
    int tg   = lane & 3;
    int m0   = (w >> 2) * 32;
    int n0   = (w & 3) * (NT * 8);

    for (int ks = 0; ks < KSTEPS; ks++) {
        int k0 = kOff + ks * 16 + 2 * tg;
        uint32_t a[2][4];
        #pragma unroll
        for (int mt = 0; mt < 2; mt++) {
            const __half* Ab = sA + (m0 + 16 * mt) * SA + k0;
            a[mt][0] = *reinterpret_cast<const uint32_t*>(Ab + g * SA);
            a[mt][1] = *reinterpret_cast<const uint32_t*>(Ab + (g + 8) * SA);
            a[mt][2] = *reinterpret_cast<const uint32_t*>(Ab + g * SA + 8);
            a[mt][3] = *reinterpret_cast<const uint32_t*>(Ab + (g + 8) * SA + 8);
        }
        #pragma unroll
        for (int nt = 0; nt < NT; nt++) {
            const __half* Wb = sW + (n0 + 8 * nt + g) * KH + k0;
            uint32_t bfr[2];
            bfr[0] = *reinterpret_cast<const uint32_t*>(Wb);
            bfr[1] = *reinterpret_cast<const uint32_t*>(Wb + 8);
            mma_f16(acc[0][nt], a[0], bfr);
            mma_f16(acc[1][nt], a[1], bfr);
        }
    }
}

// writes fp16(relu(acc+bias)) into sOut
template<int NT, int SOUT>
__device__ __forceinline__ void epi_relu(float (&acc)[2][NT][4],
                                         const float* __restrict__ gBias,
                                         __half* __restrict__ sOut)
{
    int lane = threadIdx.x & 31;
    int w    = threadIdx.x >> 5;
    int g    = lane >> 2;
    int tg   = lane & 3;
    int m0   = (w >> 2) * 32;
    int n0   = (w & 3) * (NT * 8);
    #pragma unroll
    for (int mt = 0; mt < 2; mt++)
        #pragma unroll
        for (int nt = 0; nt < NT; nt++) {
            int row = m0 + 16 * mt + g;
            int col = n0 + 8 * nt + 2 * tg;
            float b0v = gBias[col], b1v = gBias[col + 1];
            sOut[row * SOUT + col]           = __float2half(fmaxf(acc[mt][nt][0] + b0v, 0.0f));
            sOut[row * SOUT + col + 1]       = __float2half(fmaxf(acc[mt][nt][1] + b1v, 0.0f));
            sOut[(row + 8) * SOUT + col]     = __float2half(fmaxf(acc[mt][nt][2] + b0v, 0.0f));
            sOut[(row + 8) * SOUT + col + 1] = __float2half(fmaxf(acc[mt][nt][3] + b1v, 0.0f));
        }
}

template<int NT, int SEG>
__device__ __forceinline__ void epi_final(float (&acc)[2][NT][4],
                                          const float* __restrict__ gBias,
                                          int* __restrict__ sMaxI,
                                          float* __restrict__ outF, int centerBase)
{
    int lane = threadIdx.x & 31;
    int w    = threadIdx.x >> 5;
    int g    = lane >> 2;
    int tg   = lane & 3;
    int n0   = (w & 3) * (NT * 8);

    if (SEG == 128) {
        #pragma unroll
        for (int nt = 0; nt < NT; nt++) {
            int col = n0 + 8 * nt + 2 * tg;
            float v0 = fmaxf(fmaxf(acc[0][nt][0], acc[0][nt][2]),
                             fmaxf(acc[1][nt][0], acc[1][nt][2]));
            float v1 = fmaxf(fmaxf(acc[0][nt][1], acc[0][nt][3]),
                             fmaxf(acc[1][nt][1], acc[1][nt][3]));
            v0 = fmaxf(v0 + gBias[col], 0.0f);
            v1 = fmaxf(v1 + gBias[col + 1], 0.0f);
            #pragma unroll
            for (int off = 4; off < 32; off <<= 1) {
                v0 = fmaxf(v0, __shfl_xor_sync(0xffffffffu, v0, off));
                v1 = fmaxf(v1, __shfl_xor_sync(0xffffffffu, v1, off));
            }
            if (g == 0) {
                atomicMax(&sMaxI[col],     __float_as_int(v0));
                atomicMax(&sMaxI[col + 1], __float_as_int(v1));
            }
        }
    } else if (SEG == 32) {
        int center = centerBase + (w >> 2);
        #pragma unroll
        for (int nt = 0; nt < NT; nt++) {
            int col = n0 + 8 * nt + 2 * tg;
            float v0 = fmaxf(fmaxf(acc[0][nt][0], acc[0][nt][2]),
                             fmaxf(acc[1][nt][0], acc[1][nt][2]));
            float v1 = fmaxf(fmaxf(acc[0][nt][1], acc[0][nt][3]),
                             fmaxf(acc[1][nt][1], acc[1][nt][3]));
            #pragma unroll
            for (int off = 4; off < 32; off <<= 1) {
                v0 = fmaxf(v0, __shfl_xor_sync(0xffffffffu, v0, off));
                v1 = fmaxf(v1, __shfl_xor_sync(0xffffffffu, v1, off));
            }
            if (g == 0) {
                float* op = outF + (size_t)center * FEAT_W;
                op[col]     = fmaxf(v0 + gBias[col], 0.0f);
                op[col + 1] = fmaxf(v1 + gBias[col + 1], 0.0f);
            }
        }
    } else { // SEG == 16: each m-tile is one center
        #pragma unroll
        for (int mt = 0; mt < 2; mt++) {
            int center = centerBase + (w >> 2) * 2 + mt;
            #pragma unroll
            for (int nt = 0; nt < NT; nt++) {
                int col = n0 + 8 * nt + 2 * tg;
                float v0 = fmaxf(acc[mt][nt][0], acc[mt][nt][2]);
                float v1 = fmaxf(acc[mt][nt][1], acc[mt][nt][3]);
                #pragma unroll
                for (int off = 4; off < 32; off <<= 1) {
                    v0 = fmaxf(v0, __shfl_xor_sync(0xffffffffu, v0, off));
                    v1 = fmaxf(v1, __shfl_xor_sync(0xffffffffu, v1, off));
                }
                if (g == 0) {
                    float* op = outF + (size_t)center * FEAT_W;
                    op[col]     = fmaxf(v0 + gBias[col], 0.0f);
                    op[col + 1] = fmaxf(v1 + gBias[col + 1], 0.0f);
                }
            }
        }
    }
}

// stage W TRANSPOSED into [NC][KH] fp16 (gW is [K][NC] row-major, KUSE rows).
template<int NC, int KH, int KUSE>
__device__ __forceinline__ void stage_wt(__half* __restrict__ sW,
                                         const float* __restrict__ gW)
{
    for (int t = threadIdx.x; t < NC * KH; t += NTH) {
        int k = t / NC;          // consecutive threads -> consecutive n (coalesced)
        int n = t - k * NC;
        sW[n * KH + k] = (k < KUSE) ? __float2half(gW[k * NC + n]) : __half(0.0f);
    }
}

// =====================================================================
// Unified fp16 MLP kernel. One block = 128 rows = (128/SEG) centers.
// buf2 aliases sIn (dead after layer 1). All weights staged whole.
// =====================================================================
template<int SEG, int C1, int C2, int C3>
__global__ __launch_bounds__(NTH, 2) void mlp_mma_kernel(
    const float* __restrict__ xyz,
    const float* __restrict__ points,
    const int* __restrict__ idxbuf,
    const float* __restrict__ W1, const float* __restrict__ B1,
    const float* __restrict__ W2, const float* __restrict__ B2,
    const float* __restrict__ W3, const float* __restrict__ B3,
    float* __restrict__ outF)
{
    constexpr int CPB  = 128 / SEG;
    constexpr int S1   = SHPAD(C1);          // buf1 stride (halves)
    constexpr int S2   = SHPAD(C2);          // buf2 stride
    constexpr int KH1  = SH_IN;              // W1 k-stride (reads to col 79)
    constexpr int KH2  = SHPAD(C1);
    constexpr int KH3  = SHPAD(C2);
    constexpr int REG0 = 128 * cmax2i(SH_IN, S2);   // sIn region, reused as buf2
    constexpr int WMAX = cmax3i(C1 * KH1, C2 * KH2, C3 * KH3);
    constexpr int NT1  = C1 / 32, NT2 = C2 / 32, NT3 = C3 / 32;
    constexpr int KS2  = C1 / 16, KS3 = C2 / 16;

    extern __shared__ __half smh[];
    __half* sIn   = smh;                    // [REG0] (later reused as buf2)
    __half* buf1  = smh + REG0;             // 128 * S1
    __half* sW    = buf1 + 128 * S1;        // WMAX
    int*    sMaxI = (int*)(sW + WMAX);      // 128
    int*    sIdx  = sMaxI + 128;            // 128

    int centerBase = blockIdx.x * CPB;
    int b = centerBase >> 10;

    for (int t = threadIdx.x; t < 128; t += NTH) {
        sIdx[t]  = idxbuf[(size_t)centerBase * SEG + t];
        sMaxI[t] = 0;
    }
    __syncthreads();

    const float* pB = points + (size_t)b * NPTS * CIN_PTS;
    const float* xB = xyz + (size_t)b * NPTS * 3;

    for (int t = threadIdx.x; t < 128 * SH_IN; t += NTH) {
        int s = t / SH_IN, c = t - s * SH_IN;
        int ci = centerBase + s / SEG;
        float v;
        if (c < 64)       v = pB[(size_t)sIdx[s] * CIN_PTS + c];
        else if (c < 67) {
            int d = c - 64;
            v = xB[(size_t)sIdx[s] * 3 + d] - g_new_xyz[ci * 3 + d];
        } else v = 0.0f;
        sIn[t] = __float2half(v);
    }
    stage_wt<C1, KH1, 67>(sW, W1);
    __syncthreads();

    // layer 1: sIn -> buf1  (K=67 padded to 80 -> 5 k16-steps)
    {
        float acc[2][NT1][4];
        #pragma unroll
        for (int mt = 0; mt < 2; mt++)
            #pragma unroll
            for (int nt = 0; nt < NT1; nt++)
                #pragma unroll
                for (int i = 0; i < 4; i++) acc[mt][nt][i] = 0.0f;
        mma_accum<5, SH_IN, KH1, NT1>(sIn, 0, sW, acc);
        epi_relu<NT1, S1>(acc, B1, buf1);
    }
    __syncthreads();

    stage_wt<C2, KH2, C1>(sW, W2);
    __syncthreads();

    // layer 2: buf1 -> buf2 (aliases sIn)
    __half* buf2 = sIn;
    {
        float acc[2][NT2][4];
        #pragma unroll
        for (int mt = 0; mt < 2; mt++)
            #pragma unroll
            for (int nt = 0; nt < NT2; nt++)
                #pragma unroll
                for (int i = 0; i < 4; i++) acc[mt][nt][i] = 0.0f;
        mma_accum<KS2, S1, KH2, NT2>(buf1, 0, sW, acc);
        epi_relu<NT2, S2>(acc, B2, buf2);
    }
    __syncthreads();

    stage_wt<C3, KH3, C2>(sW, W3);
    __syncthreads();

    // layer 3: buf2 -> maxpool output
    {
        float acc[2][NT3][4];
        #pragma unroll
        for (int mt = 0; mt < 2; mt++)
            #pragma unroll
            for (int nt = 0; nt < NT3; nt++)
                #pragma unroll
                for (int i = 0; i < 4; i++) acc[mt][nt][i] = 0.0f;
        mma_accum<KS3, S2, KH3, NT3>(buf2, 0, sW, acc);
        epi_final<NT3, SEG>(acc, B3, sMaxI, outF, centerBase);
    }

    if (SEG == 128) {
        __syncthreads();
        for (int t = threadIdx.x; t < C3; t += NTH)
            outF[(size_t)centerBase * FEAT_W + t] = __int_as_float(sMaxI[t]);
    }
}

// =====================================================================
// host launch
// =====================================================================
template<int SEG, int C1, int C2, int C3>
static constexpr int smem_mma() {
    constexpr int WMAX = cmax3i(C1 * SH_IN, C2 * SHPAD(C1), C3 * SHPAD(C2));
    constexpr int REG0 = 128 * cmax2i(SH_IN, SHPAD(C2));
    return (REG0 + 128 * SHPAD(C1) + WMAX) * 2 + 256 * 4;
}

extern "C" void kernel_launch(void* const* d_in, const int* in_sizes, int n_in,
                              void* d_out, int out_size)
{
    const float* xyz = (const float*)d_in[0];
    const float* pts = (const float*)d_in[1];
    const float* W[3][3];
    const float* Bv[3][3];
    int k = 2;
    for (int bi = 0; bi < 3; bi++)
        for (int li = 0; li < 3; li++) {
            W[bi][li]  = (const float*)d_in[k++];
            Bv[bi][li] = (const float*)d_in[k++];
        }

    float* out        = (float*)d_out;
    float* out_newxyz = out;
    float* out_feat   = out + (size_t)NCENT * 3;

    const int fps_smem = 3 * NPTS * 4;
    const int bq_smem  = 3 * NPTS * 4;
    constexpr int sm0 = smem_mma<16, 32, 32, 64>();
    constexpr int sm1 = smem_mma<32, 64, 64, 128>();
    constexpr int sm2 = smem_mma<128, 64, 96, 128>();   // ~72.7 KB

    cudaFuncSetAttribute(fps_kernel, cudaFuncAttributeMaxDynamicSharedMemorySize, fps_smem);
    cudaFuncSetAttribute((const void*)mlp_mma_kernel<16, 32, 32, 64>,
                         cudaFuncAttributeMaxDynamicSharedMemorySize, sm0);
    cudaFuncSetAttribute((const void*)mlp_mma_kernel<32, 64, 64, 128>,
                         cudaFuncAttributeMaxDynamicSharedMemorySize, sm1);
    cudaFuncSetAttribute((const void*)mlp_mma_kernel<128, 64, 96, 128>,
                         cudaFuncAttributeMaxDynamicSharedMemorySize, sm2);

    fps_kernel<<<BATCH, 256, fps_smem>>>(xyz, out_newxyz);
    bq_fused_kernel<<<NCENT / 8, 256, bq_smem>>>(xyz, g_idx0, g_idx1, g_idx2);

    mlp_mma_kernel<128, 64, 96, 128><<<NCENT, NTH, sm2>>>(
        xyz, pts, g_idx2,
        W[2][0], Bv[2][0], W[2][1], Bv[2][1], W[2][2], Bv[2][2],
        out_feat + 192);
    mlp_mma_kernel<32, 64, 64, 128><<<NCENT / 4, NTH, sm1>>>(
        xyz, pts, g_idx1,
        W[1][0], Bv[1][0], W[1][1], Bv[1][1], W[1][2], Bv[1][2],
        out_feat + 64);
    mlp_mma_kernel<16, 32, 32, 64><<<NCENT / 8, NTH, sm0>>>(
        xyz, pts, g_idx0,
        W[0][0], Bv[0][0], W[0][1], Bv[0][1], W[0][2], Bv[0][2],
        out_feat + 0);
}

// round 13
// speedup vs baseline: 1.2830x; 1.0115x over previous
#include <cuda_runtime.h>
#include <cuda_fp16.h>
#include <cstdint>

#define BATCH   8
#define NPTS    4096
#define CIN_PTS 64
#define NPOINT  1024
#define NCENT   (BATCH * NPOINT)   // 8192
#define FEAT_W  320
#define NTH     512                // threads per MLP block
#define SH_IN   88                 // sIn stride in halves (covers k reads to 79)

// ---------------- device scratch ----------------
__device__ float g_new_xyz[NCENT * 3];
__device__ int   g_idx0[NCENT * 16];
__device__ int   g_idx1[NCENT * 32];
__device__ int   g_idx2[NCENT * 128];

__host__ __device__ constexpr int cmax3i(int a, int b, int c) {
    return a > b ? (a > c ? a : c) : (b > c ? b : c);
}
__host__ __device__ constexpr int cmax2i(int a, int b) { return a > b ? a : b; }
// pad (in halves) so word-stride mod 32 in {4,12,20,28} -> conflict-free frag/LDSM loads
__host__ __device__ constexpr int SHPAD(int k) {
    int m = (k + 7) & ~7;
    while (!((m % 64 == 8) || (m % 64 == 24) || (m % 64 == 40) || (m % 64 == 56))) m += 8;
    return m;
}

// =====================================================================
// FPS: one block per batch, 256 threads x 16 register-resident points.
// =====================================================================
__global__ __launch_bounds__(256) void fps_kernel(const float* __restrict__ xyz,
                                                  float* __restrict__ out_newxyz)
{
    int b = blockIdx.x;
    extern __shared__ float sm[];
    float* sx = sm;
    float* sy = sm + NPTS;
    float* sz = sm + 2 * NPTS;
    __shared__ unsigned long long skey[3];

    const float* base = xyz + (size_t)b * NPTS * 3;
    float px[16], py[16], pz[16], pd[16];
    #pragma unroll
    for (int r = 0; r < 16; r++) {
        int p = threadIdx.x + r * 256;
        float x = base[p * 3 + 0];
        float y = base[p * 3 + 1];
        float z = base[p * 3 + 2];
        sx[p] = x; sy[p] = y; sz[p] = z;
        px[r] = x; py[r] = y; pz[r] = z;
        pd[r] = 1e10f;
    }
    if (threadIdx.x == 0) {
        skey[0] = 0xFFFFFFFFull;   // decodes to index 0
        skey[1] = 0ull;
        skey[2] = 0ull;
    }
    __syncthreads();

    int lane = threadIdx.x & 31;

    for (int it = 0; it < NPOINT; it++) {
        int cur = it % 3, nxt = (it + 1) % 3, rst = (it + 2) % 3;
        unsigned int low = (unsigned int)skey[cur];
        int far = (int)(0xFFFFFFFFu - low);

        if (threadIdx.x == 0) {
            float fx = sx[far], fy = sy[far], fz = sz[far];
            int row = b * NPOINT + it;
            out_newxyz[row * 3 + 0] = fx;
            out_newxyz[row * 3 + 1] = fy;
            out_newxyz[row * 3 + 2] = fz;
            g_new_xyz[row * 3 + 0] = fx;
            g_new_xyz[row * 3 + 1] = fy;
            g_new_xyz[row * 3 + 2] = fz;
            skey[rst] = 0ull;
        }
        float cx = sx[far], cy = sy[far], cz = sz[far];

        float bv = -1.0f;
        int   bi = 0;
        #pragma unroll
        for (int r = 0; r < 16; r++) {
            float dx = px[r] - cx;
            float dy = py[r] - cy;
            float dz = pz[r] - cz;
            float d = __fadd_rn(__fadd_rn(__fmul_rn(dx, dx), __fmul_rn(dy, dy)),
                                __fmul_rn(dz, dz));
            float nd = fminf(pd[r], d);
            pd[r] = nd;
            if (nd > bv) { bv = nd; bi = threadIdx.x + r * 256; }
        }
        #pragma unroll
        for (int off = 16; off >= 1; off >>= 1) {
            float ov = __shfl_down_sync(0xffffffffu, bv, off);
            int   oi = __shfl_down_sync(0xffffffffu, bi, off);
            if (ov > bv || (ov == bv && oi < bi)) { bv = ov; bi = oi; }
        }
        if (lane == 0) {
            unsigned long long key =
                ((unsigned long long)__float_as_uint(bv) << 32) |
                (unsigned long long)(0xFFFFFFFFu - (unsigned int)bi);
            atomicMax(&skey[nxt], key);
        }
        __syncthreads();
    }
}

// =====================================================================
// Fused ball query (3 radii, one smem-staged scan). Warp per center.
// =====================================================================
__global__ __launch_bounds__(256) void bq_fused_kernel(const float* __restrict__ xyz,
                                                       int* __restrict__ o0,
                                                       int* __restrict__ o1,
                                                       int* __restrict__ o2)
{
    extern __shared__ float sm[];
    float* sx = sm;
    float* sy = sm + NPTS;
    float* sz = sm + 2 * NPTS;

    int wid  = threadIdx.x >> 5;
    int lane = threadIdx.x & 31;
    int gw   = blockIdx.x * 8 + wid;
    int b    = gw >> 10;

    const float* base = xyz + (size_t)b * NPTS * 3;
    for (int t = threadIdx.x; t < NPTS * 3; t += 256) {
        int p = t / 3, c = t - p * 3;
        float v = base[t];
        (c == 0 ? sx : (c == 1 ? sy : sz))[p] = v;
    }
    __syncthreads();

    const float r2_0 = (float)(0.1 * 0.1);
    const float r2_1 = (float)(0.2 * 0.2);
    const float r2_2 = (float)(0.4 * 0.4);

    float cx = g_new_xyz[gw * 3 + 0];
    float cy = g_new_xyz[gw * 3 + 1];
    float cz = g_new_xyz[gw * 3 + 2];

    int* p0 = o0 + (size_t)gw * 16;
    int* p1 = o1 + (size_t)gw * 32;
    int* p2 = o2 + (size_t)gw * 128;

    int c0 = 0, c1 = 0, c2 = 0;
    int f0 = -1, f1 = -1, f2 = -1;
    unsigned lmask = (1u << lane) - 1u;

    for (int s = 0; s < NPTS; s += 32) {
        int p = s + lane;
        float dx = sx[p] - cx;
        float dy = sy[p] - cy;
        float dz = sz[p] - cz;
        float d2 = __fadd_rn(__fadd_rn(__fmul_rn(dx, dx), __fmul_rn(dy, dy)),
                             __fmul_rn(dz, dz));
        bool h0 = d2 < r2_0, h1 = d2 < r2_1, h2 = d2 < r2_2;
        unsigned m0 = __ballot_sync(0xffffffffu, h0);
        unsigned m1 = __ballot_sync(0xffffffffu, h1);
        unsigned m2 = __ballot_sync(0xffffffffu, h2);
        if (m0) {
            if (f0 < 0) f0 = s + (__ffs(m0) - 1);
            if (h0) { int pos = c0 + __popc(m0 & lmask); if (pos < 16) p0[pos] = p; }
            c0 += __popc(m0);
        }
        if (m1) {
            if (f1 < 0) f1 = s + (__ffs(m1) - 1);
            if (h1) { int pos = c1 + __popc(m1 & lmask); if (pos < 32) p1[pos] = p; }
            c1 += __popc(m1);
        }
        if (m2) {
            if (f2 < 0) f2 = s + (__ffs(m2) - 1);
            if (h2) { int pos = c2 + __popc(m2 & lmask); if (pos < 128) p2[pos] = p; }
            c2 += __popc(m2);
        }
        if (c0 >= 16 && c1 >= 32 && c2 >= 128) break;
    }
    for (int pos = c0 + lane; pos < 16; pos += 32) p0[pos] = f0;
    for (int pos = c1 + lane; pos < 32; pos += 32) p1[pos] = f1;
    for (int pos = c2 + lane; pos < 128; pos += 32) p2[pos] = f2;
}

// =====================================================================
// fp16 m16n8k16 mma pipeline with ldmatrix operand loads.
// 512 threads: 4 m-warps x 4 n-warps. W transposed [N][KH].
// =====================================================================
__device__ __forceinline__ void mma_f16(float* d, const uint32_t* a, const uint32_t* b) {
    asm volatile("mma.sync.aligned.m16n8k16.row.col.f32.f16.f16.f32 "
                 "{%0,%1,%2,%3},{%4,%5,%6,%7},{%8,%9},{%0,%1,%2,%3};"
                 : "+f"(d[0]), "+f"(d[1]), "+f"(d[2]), "+f"(d[3])
                 : "r"(a[0]), "r"(a[1]), "r"(a[2]), "r"(a[3]),
                   "r"(b[0]), "r"(b[1]));
}

__device__ __forceinline__ void ldsm_x4(uint32_t* r, uint32_t addr) {
    asm volatile("ldmatrix.sync.aligned.m8n8.x4.shared.b16 {%0,%1,%2,%3}, [%4];"
                 : "=r"(r[0]), "=r"(r[1]), "=r"(r[2]), "=r"(r[3]) : "r"(addr));
}
__device__ __forceinline__ void ldsm_x2(uint32_t* r, uint32_t addr) {
    asm volatile("ldmatrix.sync.aligned.m8n8.x2.shared.b16 {%0,%1}, [%2];"
                 : "=r"(r[0]), "=r"(r[1]) : "r"(addr));
}

__device__ __forceinline__ uint32_t smem_u32(const void* p) {
    return (uint32_t)__cvta_generic_to_shared(p);
}

// A: [rows][SA] halves; W: [N][KH] halves. KSTEPS k16-steps starting at kOff.
template<int KSTEPS, int SA, int KH, int NT>
__device__ __forceinline__ void mma_accum(const __half* __restrict__ sA, int kOff,
                                          const __half* __restrict__ sW,
                                          float (&acc)[2][NT][4])
{
    int lane = threadIdx.x & 31;
    int w    = threadIdx.x >> 5;
    int m0   = (w >> 2) * 32;
    int n0   = (w & 3) * (NT * 8);

    // ldmatrix lane-address components
    int aRow = m0 + (lane & 7) + ((lane >> 3) & 1) * 8;  // + 16*mt
    int aCol = (lane >> 4) * 8;                          // + k0
    int bRowX4 = (lane & 7) + (lane >> 4) * 8;           // + n0 + 8*nt
    int bColX4 = ((lane >> 3) & 1) * 8;                  // + k0
    int bRowX2 = (lane & 7);                             // lanes 0-15 used
    int bColX2 = (((lane >> 3) & 1) & 1) * 8;

    for (int ks = 0; ks < KSTEPS; ks++) {
        int k0 = kOff + ks * 16;
        uint32_t a[2][4];
        #pragma unroll
        for (int mt = 0; mt < 2; mt++)
            ldsm_x4(a[mt], smem_u32(sA + (aRow + 16 * mt) * SA + aCol + k0));

        uint32_t bfr[NT][2];
        #pragma unroll
        for (int nt = 0; nt < NT; nt += 2) {
            if (nt + 1 < NT) {
                uint32_t tmp[4];
                ldsm_x4(tmp, smem_u32(sW + (n0 + 8 * nt + bRowX4) * KH + bColX4 + k0));
                bfr[nt][0] = tmp[0]; bfr[nt][1] = tmp[1];
                bfr[nt + 1][0] = tmp[2]; bfr[nt + 1][1] = tmp[3];
            } else {
                ldsm_x2(bfr[nt], smem_u32(sW + (n0 + 8 * nt + bRowX2) * KH + bColX2 + k0));
            }
        }
        #pragma unroll
        for (int nt = 0; nt < NT; nt++) {
            mma_f16(acc[0][nt], a[0], bfr[nt]);
            mma_f16(acc[1][nt], a[1], bfr[nt]);
        }
    }
}

// writes fp16(relu(acc+bias)) into sOut
template<int NT, int SOUT>
__device__ __forceinline__ void epi_relu(float (&acc)[2][NT][4],
                                         const float* __restrict__ gBias,
                                         __half* __restrict__ sOut)
{
    int lane = threadIdx.x & 31;
    int w    = threadIdx.x >> 5;
    int g    = lane >> 2;
    int tg   = lane & 3;
    int m0   = (w >> 2) * 32;
    int n0   = (w & 3) * (NT * 8);
    #pragma unroll
    for (int mt = 0; mt < 2; mt++)
        #pragma unroll
        for (int nt = 0; nt < NT; nt++) {
            int row = m0 + 16 * mt + g;
            int col = n0 + 8 * nt + 2 * tg;
            float b0v = gBias[col], b1v = gBias[col + 1];
            sOut[row * SOUT + col]           = __float2half(fmaxf(acc[mt][nt][0] + b0v, 0.0f));
            sOut[row * SOUT + col + 1]       = __float2half(fmaxf(acc[mt][nt][1] + b1v, 0.0f));
            sOut[(row + 8) * SOUT + col]     = __float2half(fmaxf(acc[mt][nt][2] + b0v, 0.0f));
            sOut[(row + 8) * SOUT + col + 1] = __float2half(fmaxf(acc[mt][nt][3] + b1v, 0.0f));
        }
}

template<int NT, int SEG>
__device__ __forceinline__ void epi_final(float (&acc)[2][NT][4],
                                          const float* __restrict__ gBias,
                                          int* __restrict__ sMaxI,
                                          float* __restrict__ outF, int centerBase)
{
    int lane = threadIdx.x & 31;
    int w    = threadIdx.x >> 5;
    int g    = lane >> 2;
    int tg   = lane & 3;
    int n0   = (w & 3) * (NT * 8);

    if (SEG == 128) {
        #pragma unroll
        for (int nt = 0; nt < NT; nt++) {
            int col = n0 + 8 * nt + 2 * tg;
            float v0 = fmaxf(fmaxf(acc[0][nt][0], acc[0][nt][2]),
                             fmaxf(acc[1][nt][0], acc[1][nt][2]));
            float v1 = fmaxf(fmaxf(acc[0][nt][1], acc[0][nt][3]),
                             fmaxf(acc[1][nt][1], acc[1][nt][3]));
            v0 = fmaxf(v0 + gBias[col], 0.0f);
            v1 = fmaxf(v1 + gBias[col + 1], 0.0f);
            #pragma unroll
            for (int off = 4; off < 32; off <<= 1) {
                v0 = fmaxf(v0, __shfl_xor_sync(0xffffffffu, v0, off));
                v1 = fmaxf(v1, __shfl_xor_sync(0xffffffffu, v1, off));
            }
            if (g == 0) {
                atomicMax(&sMaxI[col],     __float_as_int(v0));
                atomicMax(&sMaxI[col + 1], __float_as_int(v1));
            }
        }
    } else if (SEG == 32) {
        int center = centerBase + (w >> 2);
        #pragma unroll
        for (int nt = 0; nt < NT; nt++) {
            int col = n0 + 8 * nt + 2 * tg;
            float v0 = fmaxf(fmaxf(acc[0][nt][0], acc[0][nt][2]),
                             fmaxf(acc[1][nt][0], acc[1][nt][2]));
            float v1 = fmaxf(fmaxf(acc[0][nt][1], acc[0][nt][3]),
                             fmaxf(acc[1][nt][1], acc[1][nt][3]));
            #pragma unroll
            for (int off = 4; off < 32; off <<= 1) {
                v0 = fmaxf(v0, __shfl_xor_sync(0xffffffffu, v0, off));
                v1 = fmaxf(v1, __shfl_xor_sync(0xffffffffu, v1, off));
            }
            if (g == 0) {
                float* op = outF + (size_t)center * FEAT_W;
                op[col]     = fmaxf(v0 + gBias[col], 0.0f);
                op[col + 1] = fmaxf(v1 + gBias[col + 1], 0.0f);
            }
        }
    } else { // SEG == 16: each m-tile is one center
        #pragma unroll
        for (int mt = 0; mt < 2; mt++) {
            int center = centerBase + (w >> 2) * 2 + mt;
            #pragma unroll
            for (int nt = 0; nt < NT; nt++) {
                int col = n0 + 8 * nt + 2 * tg;
                float v0 = fmaxf(acc[mt][nt][0], acc[mt][nt][2]);
                float v1 = fmaxf(acc[mt][nt][1], acc[mt][nt][3]);
                #pragma unroll
                for (int off = 4; off < 32; off <<= 1) {
                    v0 = fmaxf(v0, __shfl_xor_sync(0xffffffffu, v0, off));
                    v1 = fmaxf(v1, __shfl_xor_sync(0xffffffffu, v1, off));
                }
                if (g == 0) {
                    float* op = outF + (size_t)center * FEAT_W;
                    op[col]     = fmaxf(v0 + gBias[col], 0.0f);
                    op[col + 1] = fmaxf(v1 + gBias[col + 1], 0.0f);
                }
            }
        }
    }
}

// stage W TRANSPOSED into [NC][KH] fp16 (gW is [K][NC] row-major, KUSE rows).
template<int NC, int KH, int KUSE>
__device__ __forceinline__ void stage_wt(__half* __restrict__ sW,
                                         const float* __restrict__ gW)
{
    for (int t = threadIdx.x; t < NC * KH; t += NTH) {
        int k = t / NC;          // consecutive threads -> consecutive n (coalesced)
        int n = t - k * NC;
        sW[n * KH + k] = (k < KUSE) ? __float2half(gW[k * NC + n]) : __half(0.0f);
    }
}

// =====================================================================
// Unified fp16 MLP kernel. One block = 128 rows = (128/SEG) centers.
// buf2 aliases sIn (dead after layer 1). All weights staged whole.
// =====================================================================
template<int SEG, int C1, int C2, int C3>
__global__ __launch_bounds__(NTH, 2) void mlp_mma_kernel(
    const float* __restrict__ xyz,
    const float* __restrict__ points,
    const int* __restrict__ idxbuf,
    const float* __restrict__ W1, const float* __restrict__ B1,
    const float* __restrict__ W2, const float* __restrict__ B2,
    const float* __restrict__ W3, const float* __restrict__ B3,
    float* __restrict__ outF)
{
    constexpr int CPB  = 128 / SEG;
    constexpr int S1   = SHPAD(C1);          // buf1 stride (halves)
    constexpr int S2   = SHPAD(C2);          // buf2 stride
    constexpr int KH1  = SH_IN;              // W1 k-stride (reads to col 79)
    constexpr int KH2  = SHPAD(C1);
    constexpr int KH3  = SHPAD(C2);
    constexpr int REG0 = 128 * cmax2i(SH_IN, S2);   // sIn region, reused as buf2
    constexpr int WMAX = cmax3i(C1 * KH1, C2 * KH2, C3 * KH3);
    constexpr int NT1  = C1 / 32, NT2 = C2 / 32, NT3 = C3 / 32;
    constexpr int KS2  = C1 / 16, KS3 = C2 / 16;

    extern __shared__ __half smh[];
    __half* sIn   = smh;                    // [REG0] (later reused as buf2)
    __half* buf1  = smh + REG0;             // 128 * S1
    __half* sW    = buf1 + 128 * S1;        // WMAX
    int*    sMaxI = (int*)(sW + WMAX);      // 128
    int*    sIdx  = sMaxI + 128;            // 128

    int centerBase = blockIdx.x * CPB;
    int b = centerBase >> 10;

    for (int t = threadIdx.x; t < 128; t += NTH) {
        sIdx[t]  = idxbuf[(size_t)centerBase * SEG + t];
        sMaxI[t] = 0;
    }
    __syncthreads();

    const float* pB = points + (size_t)b * NPTS * CIN_PTS;
    const float* xB = xyz + (size_t)b * NPTS * 3;

    for (int t = threadIdx.x; t < 128 * SH_IN; t += NTH) {
        int s = t / SH_IN, c = t - s * SH_IN;
        int ci = centerBase + s / SEG;
        float v;
        if (c < 64)       v = pB[(size_t)sIdx[s] * CIN_PTS + c];
        else if (c < 67) {
            int d = c - 64;
            v = xB[(size_t)sIdx[s] * 3 + d] - g_new_xyz[ci * 3 + d];
        } else v = 0.0f;
        sIn[t] = __float2half(v);
    }
    stage_wt<C1, KH1, 67>(sW, W1);
    __syncthreads();

    // layer 1: sIn -> buf1  (K=67 padded to 80 -> 5 k16-steps)
    {
        float acc[2][NT1][4];
        #pragma unroll
        for (int mt = 0; mt < 2; mt++)
            #pragma unroll
            for (int nt = 0; nt < NT1; nt++)
                #pragma unroll
                for (int i = 0; i < 4; i++) acc[mt][nt][i] = 0.0f;
        mma_accum<5, SH_IN, KH1, NT1>(sIn, 0, sW, acc);
        epi_relu<NT1, S1>(acc, B1, buf1);
    }
    __syncthreads();

    stage_wt<C2, KH2, C1>(sW, W2);
    __syncthreads();

    // layer 2: buf1 -> buf2 (aliases sIn)
    __half* buf2 = sIn;
    {
        float acc[2][NT2][4];
        #pragma unroll
        for (int mt = 0; mt < 2; mt++)
            #pragma unroll
            for (int nt = 0; nt < NT2; nt++)
                #pragma unroll
                for (int i = 0; i < 4; i++) acc[mt][nt][i] = 0.0f;
        mma_accum<KS2, S1, KH2, NT2>(buf1, 0, sW, acc);
        epi_relu<NT2, S2>(acc, B2, buf2);
    }
    __syncthreads();

    stage_wt<C3, KH3, C2>(sW, W3);
    __syncthreads();

    // layer 3: buf2 -> maxpool output
    {
        float acc[2][NT3][4];
        #pragma unroll
        for (int mt = 0; mt < 2; mt++)
            #pragma unroll
            for (int nt = 0; nt < NT3; nt++)
                #pragma unroll
                for (int i = 0; i < 4; i++) acc[mt][nt][i] = 0.0f;
        mma_accum<KS3, S2, KH3, NT3>(buf2, 0, sW, acc);
        epi_final<NT3, SEG>(acc, B3, sMaxI, outF, centerBase);
    }

    if (SEG == 128) {
        __syncthreads();
        for (int t = threadIdx.x; t < C3; t += NTH)
            outF[(size_t)centerBase * FEAT_W + t] = __int_as_float(sMaxI[t]);
    }
}

// =====================================================================
// host launch
// =====================================================================
template<int SEG, int C1, int C2, int C3>
static constexpr int smem_mma() {
    constexpr int WMAX = cmax3i(C1 * SH_IN, C2 * SHPAD(C1), C3 * SHPAD(C2));
    constexpr int REG0 = 128 * cmax2i(SH_IN, SHPAD(C2));
    return (REG0 + 128 * SHPAD(C1) + WMAX) * 2 + 256 * 4;
}

extern "C" void kernel_launch(void* const* d_in, const int* in_sizes, int n_in,
                              void* d_out, int out_size)
{
    const float* xyz = (const float*)d_in[0];
    const float* pts = (const float*)d_in[1];
    const float* W[3][3];
    const float* Bv[3][3];
    int k = 2;
    for (int bi = 0; bi < 3; bi++)
        for (int li = 0; li < 3; li++) {
            W[bi][li]  = (const float*)d_in[k++];
            Bv[bi][li] = (const float*)d_in[k++];
        }

    float* out        = (float*)d_out;
    float* out_newxyz = out;
    float* out_feat   = out + (size_t)NCENT * 3;

    const int fps_smem = 3 * NPTS * 4;
    const int bq_smem  = 3 * NPTS * 4;
    constexpr int sm0 = smem_mma<16, 32, 32, 64>();
    constexpr int sm1 = smem_mma<32, 64, 64, 128>();
    constexpr int sm2 = smem_mma<128, 64, 96, 128>();   // ~72.7 KB

    cudaFuncSetAttribute(fps_kernel, cudaFuncAttributeMaxDynamicSharedMemorySize, fps_smem);
    cudaFuncSetAttribute((const void*)mlp_mma_kernel<16, 32, 32, 64>,
                         cudaFuncAttributeMaxDynamicSharedMemorySize, sm0);
    cudaFuncSetAttribute((const void*)mlp_mma_kernel<32, 64, 64, 128>,
                         cudaFuncAttributeMaxDynamicSharedMemorySize, sm1);
    cudaFuncSetAttribute((const void*)mlp_mma_kernel<128, 64, 96, 128>,
                         cudaFuncAttributeMaxDynamicSharedMemorySize, sm2);

    fps_kernel<<<BATCH, 256, fps_smem>>>(xyz, out_newxyz);
    bq_fused_kernel<<<NCENT / 8, 256, bq_smem>>>(xyz, g_idx0, g_idx1, g_idx2);

    mlp_mma_kernel<128, 64, 96, 128><<<NCENT, NTH, sm2>>>(
        xyz, pts, g_idx2,
        W[2][0], Bv[2][0], W[2][1], Bv[2][1], W[2][2], Bv[2][2],
        out_feat + 192);
    mlp_mma_kernel<32, 64, 64, 128><<<NCENT / 4, NTH, sm1>>>(
        xyz, pts, g_idx1,
        W[1][0], Bv[1][0], W[1][1], Bv[1][1], W[1][2], Bv[1][2],
        out_feat + 64);
    mlp_mma_kernel<16, 32, 32, 64><<<NCENT / 8, NTH, sm0>>>(
        xyz, pts, g_idx0,
        W[0][0], Bv[0][0], W[0][1], Bv[0][1], W[0][2], Bv[0][2],
        out_feat + 0);
}

// round 14
// speedup vs baseline: 1.7121x; 1.3345x over previous
#include <cuda_runtime.h>
#include <cuda_fp16.h>
#include <cstdint>

#define BATCH   8
#define NPTS    4096
#define CIN_PTS 64
#define NPOINT  1024
#define NCENT   (BATCH * NPOINT)   // 8192
#define FEAT_W  320
#define NTH     512                // threads per MLP block
#define SH_IN   88                 // sIn stride in halves (covers k reads to 79)

// ---------------- device scratch ----------------
__device__ float g_new_xyz[NCENT * 3];
__device__ int   g_idx0[NCENT * 16];
__device__ int   g_idx1[NCENT * 32];
__device__ int   g_idx2[NCENT * 128];
__device__ __align__(16) __half g_pts_h[BATCH * NPTS * CIN_PTS];  // 4 MB fp16 points
__device__ __align__(16) __half g_w_h[52000];                     // padded transposed weights

__host__ __device__ constexpr int cmax3i(int a, int b, int c) {
    return a > b ? (a > c ? a : c) : (b > c ? b : c);
}
__host__ __device__ constexpr int cmax2i(int a, int b) { return a > b ? a : b; }
// pad (in halves) so word-stride mod 32 in {4,12,20,28} -> conflict-free frag/LDSM loads
__host__ __device__ constexpr int SHPAD(int k) {
    int m = (k + 7) & ~7;
    while (!((m % 64 == 8) || (m % 64 == 24) || (m % 64 == 40) || (m % 64 == 56))) m += 8;
    return m;
}

// weight image offsets (halves), all 16B aligned
// s0: W1[32][88]@0  W2[32][40]@2816  W3[64][40]@4096
// s1: W1[64][88]@6656 W2[64][72]@12288 W3[128][72]@16896
// s2: W1[64][88]@26112 W2[96][72]@31744 W3[128][104]@38656
#define OW1_S0 0
#define OW2_S0 2816
#define OW3_S0 4096
#define OW1_S1 6656
#define OW2_S1 12288
#define OW3_S1 16896
#define OW1_S2 26112
#define OW2_S2 31744
#define OW3_S2 38656

// =====================================================================
// prep kernels
// =====================================================================
__global__ __launch_bounds__(512) void prep_pts_kernel(const float* __restrict__ pts)
{
    int i = blockIdx.x * 512 + threadIdx.x;     // over 2M/4 float4s
    float4 v = reinterpret_cast<const float4*>(pts)[i];
    __half2* o = reinterpret_cast<__half2*>(g_pts_h + (size_t)i * 4);
    o[0] = __floats2half2_rn(v.x, v.y);
    o[1] = __floats2half2_rn(v.z, v.w);
}

struct WPrep {
    const float* src[9];
    int dst[9], kuse[9], nc[9], kh[9];
};

__global__ __launch_bounds__(256) void prep_w_kernel(WPrep p)
{
    int stride = gridDim.x * 256;
    for (int m = 0; m < 9; m++) {
        int nc = p.nc[m], kh = p.kh[m], ku = p.kuse[m], dst = p.dst[m];
        const float* src = p.src[m];
        for (int t = blockIdx.x * 256 + threadIdx.x; t < nc * kh; t += stride) {
            int n = t / kh, k = t - n * kh;
            g_w_h[dst + t] = (k < ku) ? __float2half(src[k * nc + n]) : __half(0.0f);
        }
    }
}

// =====================================================================
// FPS: one block per batch, 256 threads x 16 register-resident points.
// =====================================================================
__global__ __launch_bounds__(256) void fps_kernel(const float* __restrict__ xyz,
                                                  float* __restrict__ out_newxyz)
{
    int b = blockIdx.x;
    extern __shared__ float sm[];
    float* sx = sm;
    float* sy = sm + NPTS;
    float* sz = sm + 2 * NPTS;
    __shared__ unsigned long long skey[3];

    const float* base = xyz + (size_t)b * NPTS * 3;
    float px[16], py[16], pz[16], pd[16];
    #pragma unroll
    for (int r = 0; r < 16; r++) {
        int p = threadIdx.x + r * 256;
        float x = base[p * 3 + 0];
        float y = base[p * 3 + 1];
        float z = base[p * 3 + 2];
        sx[p] = x; sy[p] = y; sz[p] = z;
        px[r] = x; py[r] = y; pz[r] = z;
        pd[r] = 1e10f;
    }
    if (threadIdx.x == 0) {
        skey[0] = 0xFFFFFFFFull;   // decodes to index 0
        skey[1] = 0ull;
        skey[2] = 0ull;
    }
    __syncthreads();

    int lane = threadIdx.x & 31;

    for (int it = 0; it < NPOINT; it++) {
        int cur = it % 3, nxt = (it + 1) % 3, rst = (it + 2) % 3;
        unsigned int low = (unsigned int)skey[cur];
        int far = (int)(0xFFFFFFFFu - low);

        if (threadIdx.x == 0) {
            float fx = sx[far], fy = sy[far], fz = sz[far];
            int row = b * NPOINT + it;
            out_newxyz[row * 3 + 0] = fx;
            out_newxyz[row * 3 + 1] = fy;
            out_newxyz[row * 3 + 2] = fz;
            g_new_xyz[row * 3 + 0] = fx;
            g_new_xyz[row * 3 + 1] = fy;
            g_new_xyz[row * 3 + 2] = fz;
            skey[rst] = 0ull;
        }
        float cx = sx[far], cy = sy[far], cz = sz[far];

        float bv = -1.0f;
        int   bi = 0;
        #pragma unroll
        for (int r = 0; r < 16; r++) {
            float dx = px[r] - cx;
            float dy = py[r] - cy;
            float dz = pz[r] - cz;
            float d = __fadd_rn(__fadd_rn(__fmul_rn(dx, dx), __fmul_rn(dy, dy)),
                                __fmul_rn(dz, dz));
            float nd = fminf(pd[r], d);
            pd[r] = nd;
            if (nd > bv) { bv = nd; bi = threadIdx.x + r * 256; }
        }
        #pragma unroll
        for (int off = 16; off >= 1; off >>= 1) {
            float ov = __shfl_down_sync(0xffffffffu, bv, off);
            int   oi = __shfl_down_sync(0xffffffffu, bi, off);
            if (ov > bv || (ov == bv && oi < bi)) { bv = ov; bi = oi; }
        }
        if (lane == 0) {
            unsigned long long key =
                ((unsigned long long)__float_as_uint(bv) << 32) |
                (unsigned long long)(0xFFFFFFFFu - (unsigned int)bi);
            atomicMax(&skey[nxt], key);
        }
        __syncthreads();
    }
}

// =====================================================================
// Fused ball query (3 radii, one smem-staged scan). Warp per center.
// =====================================================================
__global__ __launch_bounds__(256) void bq_fused_kernel(const float* __restrict__ xyz,
                                                       int* __restrict__ o0,
                                                       int* __restrict__ o1,
                                                       int* __restrict__ o2)
{
    extern __shared__ float sm[];
    float* sx = sm;
    float* sy = sm + NPTS;
    float* sz = sm + 2 * NPTS;

    int wid  = threadIdx.x >> 5;
    int lane = threadIdx.x & 31;
    int gw   = blockIdx.x * 8 + wid;
    int b    = gw >> 10;

    const float* base = xyz + (size_t)b * NPTS * 3;
    for (int t = threadIdx.x; t < NPTS * 3; t += 256) {
        int p = t / 3, c = t - p * 3;
        float v = base[t];
        (c == 0 ? sx : (c == 1 ? sy : sz))[p] = v;
    }
    __syncthreads();

    const float r2_0 = (float)(0.1 * 0.1);
    const float r2_1 = (float)(0.2 * 0.2);
    const float r2_2 = (float)(0.4 * 0.4);

    float cx = g_new_xyz[gw * 3 + 0];
    float cy = g_new_xyz[gw * 3 + 1];
    float cz = g_new_xyz[gw * 3 + 2];

    int* p0 = o0 + (size_t)gw * 16;
    int* p1 = o1 + (size_t)gw * 32;
    int* p2 = o2 + (size_t)gw * 128;

    int c0 = 0, c1 = 0, c2 = 0;
    int f0 = -1, f1 = -1, f2 = -1;
    unsigned lmask = (1u << lane) - 1u;

    for (int s = 0; s < NPTS; s += 32) {
        int p = s + lane;
        float dx = sx[p] - cx;
        float dy = sy[p] - cy;
        float dz = sz[p] - cz;
        float d2 = __fadd_rn(__fadd_rn(__fmul_rn(dx, dx), __fmul_rn(dy, dy)),
                             __fmul_rn(dz, dz));
        bool h0 = d2 < r2_0, h1 = d2 < r2_1, h2 = d2 < r2_2;
        unsigned m0 = __ballot_sync(0xffffffffu, h0);
        unsigned m1 = __ballot_sync(0xffffffffu, h1);
        unsigned m2 = __ballot_sync(0xffffffffu, h2);
        if (m0) {
            if (f0 < 0) f0 = s + (__ffs(m0) - 1);
            if (h0) { int pos = c0 + __popc(m0 & lmask); if (pos < 16) p0[pos] = p; }
            c0 += __popc(m0);
        }
        if (m1) {
            if (f1 < 0) f1 = s + (__ffs(m1) - 1);
            if (h1) { int pos = c1 + __popc(m1 & lmask); if (pos < 32) p1[pos] = p; }
            c1 += __popc(m1);
        }
        if (m2) {
            if (f2 < 0) f2 = s + (__ffs(m2) - 1);
            if (h2) { int pos = c2 + __popc(m2 & lmask); if (pos < 128) p2[pos] = p; }
            c2 += __popc(m2);
        }
        if (c0 >= 16 && c1 >= 32 && c2 >= 128) break;
    }
    for (int pos = c0 + lane; pos < 16; pos += 32) p0[pos] = f0;
    for (int pos = c1 + lane; pos < 32; pos += 32) p1[pos] = f1;
    for (int pos = c2 + lane; pos < 128; pos += 32) p2[pos] = f2;
}

// =====================================================================
// fp16 m16n8k16 mma pipeline with ldmatrix operand loads.
// 512 threads: 4 m-warps x 4 n-warps. W pre-transposed [N][KH] in g_w_h.
// =====================================================================
__device__ __forceinline__ void mma_f16(float* d, const uint32_t* a, const uint32_t* b) {
    asm volatile("mma.sync.aligned.m16n8k16.row.col.f32.f16.f16.f32 "
                 "{%0,%1,%2,%3},{%4,%5,%6,%7},{%8,%9},{%0,%1,%2,%3};"
                 : "+f"(d[0]), "+f"(d[1]), "+f"(d[2]), "+f"(d[3])
                 : "r"(a[0]), "r"(a[1]), "r"(a[2]), "r"(a[3]),
                   "r"(b[0]), "r"(b[1]));
}

__device__ __forceinline__ void ldsm_x4(uint32_t* r, uint32_t addr) {
    asm volatile("ldmatrix.sync.aligned.m8n8.x4.shared.b16 {%0,%1,%2,%3}, [%4];"
                 : "=r"(r[0]), "=r"(r[1]), "=r"(r[2]), "=r"(r[3]) : "r"(addr));
}
__device__ __forceinline__ void ldsm_x2(uint32_t* r, uint32_t addr) {
    asm volatile("ldmatrix.sync.aligned.m8n8.x2.shared.b16 {%0,%1}, [%2];"
                 : "=r"(r[0]), "=r"(r[1]) : "r"(addr));
}

__device__ __forceinline__ uint32_t smem_u32(const void* p) {
    return (uint32_t)__cvta_generic_to_shared(p);
}

// A: [rows][SA] halves; W: [N][KH] halves. KSTEPS k16-steps starting at kOff.
template<int KSTEPS, int SA, int KH, int NT>
__device__ __forceinline__ void mma_accum(const __half* __restrict__ sA, int kOff,
                                          const __half* __restrict__ sW,
                                          float (&acc)[2][NT][4])
{
    int lane = threadIdx.x & 31;
    int w    = threadIdx.x >> 5;
    int m0   = (w >> 2) * 32;
    int n0   = (w & 3) * (NT * 8);

    int aRow = m0 + (lane & 7) + ((lane >> 3) & 1) * 8;
    int aCol = (lane >> 4) * 8;
    int bRowX4 = (lane & 7) + (lane >> 4) * 8;
    int bColX4 = ((lane >> 3) & 1) * 8;
    int bRowX2 = (lane & 7);
    int bColX2 = ((lane >> 3) & 1) * 8;

    for (int ks = 0; ks < KSTEPS; ks++) {
        int k0 = kOff + ks * 16;
        uint32_t a[2][4];
        #pragma unroll
        for (int mt = 0; mt < 2; mt++)
            ldsm_x4(a[mt], smem_u32(sA + (aRow + 16 * mt) * SA + aCol + k0));

        uint32_t bfr[NT][2];
        #pragma unroll
        for (int nt = 0; nt < NT; nt += 2) {
            if (nt + 1 < NT) {
                uint32_t tmp[4];
                ldsm_x4(tmp, smem_u32(sW + (n0 + 8 * nt + bRowX4) * KH + bColX4 + k0));
                bfr[nt][0] = tmp[0]; bfr[nt][1] = tmp[1];
                bfr[nt + 1][0] = tmp[2]; bfr[nt + 1][1] = tmp[3];
            } else {
                ldsm_x2(bfr[nt], smem_u32(sW + (n0 + 8 * nt + bRowX2) * KH + bColX2 + k0));
            }
        }
        #pragma unroll
        for (int nt = 0; nt < NT; nt++) {
            mma_f16(acc[0][nt], a[0], bfr[nt]);
            mma_f16(acc[1][nt], a[1], bfr[nt]);
        }
    }
}

// writes fp16(relu(acc+bias)) into sOut
template<int NT, int SOUT>
__device__ __forceinline__ void epi_relu(float (&acc)[2][NT][4],
                                         const float* __restrict__ gBias,
                                         __half* __restrict__ sOut)
{
    int lane = threadIdx.x & 31;
    int w    = threadIdx.x >> 5;
    int g    = lane >> 2;
    int tg   = lane & 3;
    int m0   = (w >> 2) * 32;
    int n0   = (w & 3) * (NT * 8);
    #pragma unroll
    for (int mt = 0; mt < 2; mt++)
        #pragma unroll
        for (int nt = 0; nt < NT; nt++) {
            int row = m0 + 16 * mt + g;
            int col = n0 + 8 * nt + 2 * tg;
            float b0v = gBias[col], b1v = gBias[col + 1];
            sOut[row * SOUT + col]           = __float2half(fmaxf(acc[mt][nt][0] + b0v, 0.0f));
            sOut[row * SOUT + col + 1]       = __float2half(fmaxf(acc[mt][nt][1] + b1v, 0.0f));
            sOut[(row + 8) * SOUT + col]     = __float2half(fmaxf(acc[mt][nt][2] + b0v, 0.0f));
            sOut[(row + 8) * SOUT + col + 1] = __float2half(fmaxf(acc[mt][nt][3] + b1v, 0.0f));
        }
}

template<int NT, int SEG>
__device__ __forceinline__ void epi_final(float (&acc)[2][NT][4],
                                          const float* __restrict__ gBias,
                                          int* __restrict__ sMaxI,
                                          float* __restrict__ outF, int centerBase)
{
    int lane = threadIdx.x & 31;
    int w    = threadIdx.x >> 5;
    int g    = lane >> 2;
    int tg   = lane & 3;
    int n0   = (w & 3) * (NT * 8);

    if (SEG == 128) {
        #pragma unroll
        for (int nt = 0; nt < NT; nt++) {
            int col = n0 + 8 * nt + 2 * tg;
            float v0 = fmaxf(fmaxf(acc[0][nt][0], acc[0][nt][2]),
                             fmaxf(acc[1][nt][0], acc[1][nt][2]));
            float v1 = fmaxf(fmaxf(acc[0][nt][1], acc[0][nt][3]),
                             fmaxf(acc[1][nt][1], acc[1][nt][3]));
            v0 = fmaxf(v0 + gBias[col], 0.0f);
            v1 = fmaxf(v1 + gBias[col + 1], 0.0f);
            #pragma unroll
            for (int off = 4; off < 32; off <<= 1) {
                v0 = fmaxf(v0, __shfl_xor_sync(0xffffffffu, v0, off));
                v1 = fmaxf(v1, __shfl_xor_sync(0xffffffffu, v1, off));
            }
            if (g == 0) {
                atomicMax(&sMaxI[col],     __float_as_int(v0));
                atomicMax(&sMaxI[col + 1], __float_as_int(v1));
            }
        }
    } else if (SEG == 32) {
        int center = centerBase + (w >> 2);
        #pragma unroll
        for (int nt = 0; nt < NT; nt++) {
            int col = n0 + 8 * nt + 2 * tg;
            float v0 = fmaxf(fmaxf(acc[0][nt][0], acc[0][nt][2]),
                             fmaxf(acc[1][nt][0], acc[1][nt][2]));
            float v1 = fmaxf(fmaxf(acc[0][nt][1], acc[0][nt][3]),
                             fmaxf(acc[1][nt][1], acc[1][nt][3]));
            #pragma unroll
            for (int off = 4; off < 32; off <<= 1) {
                v0 = fmaxf(v0, __shfl_xor_sync(0xffffffffu, v0, off));
                v1 = fmaxf(v1, __shfl_xor_sync(0xffffffffu, v1, off));
            }
            if (g == 0) {
                float* op = outF + (size_t)center * FEAT_W;
                op[col]     = fmaxf(v0 + gBias[col], 0.0f);
                op[col + 1] = fmaxf(v1 + gBias[col + 1], 0.0f);
            }
        }
    } else { // SEG == 16
        #pragma unroll
        for (int mt = 0; mt < 2; mt++) {
            int center = centerBase + (w >> 2) * 2 + mt;
            #pragma unroll
            for (int nt = 0; nt < NT; nt++) {
                int col = n0 + 8 * nt + 2 * tg;
                float v0 = fmaxf(acc[mt][nt][0], acc[mt][nt][2]);
                float v1 = fmaxf(acc[mt][nt][1], acc[mt][nt][3]);
                #pragma unroll
                for (int off = 4; off < 32; off <<= 1) {
                    v0 = fmaxf(v0, __shfl_xor_sync(0xffffffffu, v0, off));
                    v1 = fmaxf(v1, __shfl_xor_sync(0xffffffffu, v1, off));
                }
                if (g == 0) {
                    float* op = outF + (size_t)center * FEAT_W;
                    op[col]     = fmaxf(v0 + gBias[col], 0.0f);
                    op[col + 1] = fmaxf(v1 + gBias[col + 1], 0.0f);
                }
            }
        }
    }
}

// straight vectorized copy of a pre-transposed weight image into smem
template<int NHALVES>
__device__ __forceinline__ void stage_copy(__half* __restrict__ sW,
                                           const __half* __restrict__ gW)
{
    static_assert(NHALVES % 8 == 0, "16B granularity");
    for (int t = threadIdx.x; t < NHALVES / 8; t += NTH)
        reinterpret_cast<uint4*>(sW)[t] = reinterpret_cast<const uint4*>(gW)[t];
}

// =====================================================================
// Unified fp16 MLP kernel. One block = 128 rows = (128/SEG) centers.
// buf2 aliases sIn. Weights from pre-converted g_w_h at template offsets.
// =====================================================================
template<int SEG, int C1, int C2, int C3, int OW1, int OW2, int OW3>
__global__ __launch_bounds__(NTH, 2) void mlp_mma_kernel(
    const float* __restrict__ xyz,
    const int* __restrict__ idxbuf,
    const float* __restrict__ B1,
    const float* __restrict__ B2,
    const float* __restrict__ B3,
    float* __restrict__ outF)
{
    constexpr int CPB  = 128 / SEG;
    constexpr int S1   = SHPAD(C1);
    constexpr int S2   = SHPAD(C2);
    constexpr int KH1  = SH_IN;
    constexpr int KH2  = SHPAD(C1);
    constexpr int KH3  = SHPAD(C2);
    constexpr int REG0 = 128 * cmax2i(SH_IN, S2);
    constexpr int WMAX = cmax3i(C1 * KH1, C2 * KH2, C3 * KH3);
    constexpr int NT1  = C1 / 32, NT2 = C2 / 32, NT3 = C3 / 32;
    constexpr int KS2  = C1 / 16, KS3 = C2 / 16;

    extern __shared__ __half smh[];
    __half* sIn   = smh;                    // [REG0] (later reused as buf2)
    __half* buf1  = smh + REG0;             // 128 * S1
    __half* sW    = buf1 + 128 * S1;        // WMAX
    int*    sMaxI = (int*)(sW + WMAX);      // 128
    int*    sIdx  = sMaxI + 128;            // 128

    int centerBase = blockIdx.x * CPB;
    int b = centerBase >> 10;

    for (int t = threadIdx.x; t < 128; t += NTH) {
        sIdx[t]  = idxbuf[(size_t)centerBase * SEG + t];
        sMaxI[t] = 0;
    }
    __syncthreads();

    const __half* pH = g_pts_h + (size_t)b * NPTS * CIN_PTS;
    const float*  xB = xyz + (size_t)b * NPTS * 3;

    // points channels 0..63: vectorized fp16 copy (8 halves per op)
    for (int t = threadIdx.x; t < 128 * 8; t += NTH) {
        int s = t >> 3, c = t & 7;
        uint4 v = *reinterpret_cast<const uint4*>(pH + (size_t)sIdx[s] * CIN_PTS + c * 8);
        *reinterpret_cast<uint4*>(sIn + s * SH_IN + c * 8) = v;
    }
    // cols 64..79: xyz diff (64-66) + zero pad (67-79)
    for (int t = threadIdx.x; t < 128 * 16; t += NTH) {
        int s = t >> 4, c = 64 + (t & 15);
        __half v = __half(0.0f);
        if (c < 67) {
            int d = c - 64;
            int ci = centerBase + s / SEG;
            v = __float2half(xB[(size_t)sIdx[s] * 3 + d] - g_new_xyz[ci * 3 + d]);
        }
        sIn[s * SH_IN + c] = v;
    }
    stage_copy<C1 * KH1>(sW, g_w_h + OW1);
    __syncthreads();

    // layer 1: sIn -> buf1  (K=67 padded to 80 -> 5 k16-steps)
    {
        float acc[2][NT1][4];
        #pragma unroll
        for (int mt = 0; mt < 2; mt++)
            #pragma unroll
            for (int nt = 0; nt < NT1; nt++)
                #pragma unroll
                for (int i = 0; i < 4; i++) acc[mt][nt][i] = 0.0f;
        mma_accum<5, SH_IN, KH1, NT1>(sIn, 0, sW, acc);
        epi_relu<NT1, S1>(acc, B1, buf1);
    }
    __syncthreads();

    stage_copy<C2 * KH2>(sW, g_w_h + OW2);
    __syncthreads();

    // layer 2: buf1 -> buf2 (aliases sIn)
    __half* buf2 = sIn;
    {
        float acc[2][NT2][4];
        #pragma unroll
        for (int mt = 0; mt < 2; mt++)
            #pragma unroll
            for (int nt = 0; nt < NT2; nt++)
                #pragma unroll
                for (int i = 0; i < 4; i++) acc[mt][nt][i] = 0.0f;
        mma_accum<KS2, S1, KH2, NT2>(buf1, 0, sW, acc);
        epi_relu<NT2, S2>(acc, B2, buf2);
    }
    __syncthreads();

    stage_copy<C3 * KH3>(sW, g_w_h + OW3);
    __syncthreads();

    // layer 3: buf2 -> maxpool output
    {
        float acc[2][NT3][4];
        #pragma unroll
        for (int mt = 0; mt < 2; mt++)
            #pragma unroll
            for (int nt = 0; nt < NT3; nt++)
                #pragma unroll
                for (int i = 0; i < 4; i++) acc[mt][nt][i] = 0.0f;
        mma_accum<KS3, S2, KH3, NT3>(buf2, 0, sW, acc);
        epi_final<NT3, SEG>(acc, B3, sMaxI, outF, centerBase);
    }

    if (SEG == 128) {
        __syncthreads();
        for (int t = threadIdx.x; t < C3; t += NTH)
            outF[(size_t)centerBase * FEAT_W + t] = __int_as_float(sMaxI[t]);
    }
}

// =====================================================================
// host launch
// =====================================================================
template<int SEG, int C1, int C2, int C3>
static constexpr int smem_mma() {
    constexpr int WMAX = cmax3i(C1 * SH_IN, C2 * SHPAD(C1), C3 * SHPAD(C2));
    constexpr int REG0 = 128 * cmax2i(SH_IN, SHPAD(C2));
    return (REG0 + 128 * SHPAD(C1) + WMAX) * 2 + 256 * 4;
}

extern "C" void kernel_launch(void* const* d_in, const int* in_sizes, int n_in,
                              void* d_out, int out_size)
{
    const float* xyz = (const float*)d_in[0];
    const float* pts = (const float*)d_in[1];
    const float* W[3][3];
    const float* Bv[3][3];
    int k = 2;
    for (int bi = 0; bi < 3; bi++)
        for (int li = 0; li < 3; li++) {
            W[bi][li]  = (const float*)d_in[k++];
            Bv[bi][li] = (const float*)d_in[k++];
        }

    float* out        = (float*)d_out;
    float* out_newxyz = out;
    float* out_feat   = out + (size_t)NCENT * 3;

    const int fps_smem = 3 * NPTS * 4;
    const int bq_smem  = 3 * NPTS * 4;
    constexpr int sm0 = smem_mma<16, 32, 32, 64>();
    constexpr int sm1 = smem_mma<32, 64, 64, 128>();
    constexpr int sm2 = smem_mma<128, 64, 96, 128>();

    cudaFuncSetAttribute(fps_kernel, cudaFuncAttributeMaxDynamicSharedMemorySize, fps_smem);
    cudaFuncSetAttribute((const void*)mlp_mma_kernel<16, 32, 32, 64, OW1_S0, OW2_S0, OW3_S0>,
                         cudaFuncAttributeMaxDynamicSharedMemorySize, sm0);
    cudaFuncSetAttribute((const void*)mlp_mma_kernel<32, 64, 64, 128, OW1_S1, OW2_S1, OW3_S1>,
                         cudaFuncAttributeMaxDynamicSharedMemorySize, sm1);
    cudaFuncSetAttribute((const void*)mlp_mma_kernel<128, 64, 96, 128, OW1_S2, OW2_S2, OW3_S2>,
                         cudaFuncAttributeMaxDynamicSharedMemorySize, sm2);

    // prep: fp16 points + padded transposed fp16 weights
    prep_pts_kernel<<<(BATCH * NPTS * CIN_PTS / 4) / 512, 512>>>(pts);
    WPrep wp;
    const float* srcs[9] = { W[0][0], W[0][1], W[0][2],
                             W[1][0], W[1][1], W[1][2],
                             W[2][0], W[2][1], W[2][2] };
    int dsts[9] = { OW1_S0, OW2_S0, OW3_S0, OW1_S1, OW2_S1, OW3_S1, OW1_S2, OW2_S2, OW3_S2 };
    int kus[9]  = { 67, 32, 32, 67, 64, 64, 67, 64, 96 };
    int ncs[9]  = { 32, 32, 64, 64, 64, 128, 64, 96, 128 };
    int khs[9]  = { 88, 40, 40, 88, 72, 72, 88, 72, 104 };
    for (int i = 0; i < 9; i++) {
        wp.src[i] = srcs[i]; wp.dst[i] = dsts[i];
        wp.kuse[i] = kus[i]; wp.nc[i] = ncs[i]; wp.kh[i] = khs[i];
    }
    prep_w_kernel<<<64, 256>>>(wp);

    fps_kernel<<<BATCH, 256, fps_smem>>>(xyz, out_newxyz);
    bq_fused_kernel<<<NCENT / 8, 256, bq_smem>>>(xyz, g_idx0, g_idx1, g_idx2);

    mlp_mma_kernel<128, 64, 96, 128, OW1_S2, OW2_S2, OW3_S2><<<NCENT, NTH, sm2>>>(
        xyz, g_idx2, Bv[2][0], Bv[2][1], Bv[2][2], out_feat + 192);
    mlp_mma_kernel<32, 64, 64, 128, OW1_S1, OW2_S1, OW3_S1><<<NCENT / 4, NTH, sm1>>>(
        xyz, g_idx1, Bv[1][0], Bv[1][1], Bv[1][2], out_feat + 64);
    mlp_mma_kernel<16, 32, 32, 64, OW1_S0, OW2_S0, OW3_S0><<<NCENT / 8, NTH, sm0>>>(
        xyz, g_idx0, Bv[0][0], Bv[0][1], Bv[0][2], out_feat + 0);
}

// round 16
// speedup vs baseline: 1.7616x; 1.0289x over previous
#include <cuda_runtime.h>
#include <cuda_fp16.h>
#include <cstdint>

#define BATCH   8
#define NPTS    4096
#define CIN_PTS 64
#define NPOINT  1024
#define NCENT   (BATCH * NPOINT)   // 8192
#define FEAT_W  320
#define NTH     512                // threads per MLP block
#define SH_IN   88                 // sIn stride in halves (covers k reads to 79)
#define PGRID   304                // persistent grid (2 per SM on 152 SMs)

// ---------------- device scratch ----------------
__device__ float g_new_xyz[NCENT * 3];
__device__ int   g_idx0[NCENT * 16];
__device__ int   g_idx1[NCENT * 32];
__device__ int   g_idx2[NCENT * 128];
__device__ __align__(16) __half g_pts_h[BATCH * NPTS * CIN_PTS];  // 4 MB fp16 points
__device__ __align__(16) __half g_w_h[52000];                     // padded transposed weights

__host__ __device__ constexpr int cmax3i(int a, int b, int c) {
    return a > b ? (a > c ? a : c) : (b > c ? b : c);
}
__host__ __device__ constexpr int cmax2i(int a, int b) { return a > b ? a : b; }
__host__ __device__ constexpr int SHPAD(int k) {
    int m = (k + 7) & ~7;
    while (!((m % 64 == 8) || (m % 64 == 24) || (m % 64 == 40) || (m % 64 == 56))) m += 8;
    return m;
}

// weight image offsets (halves), all 16B aligned
#define OW1_S0 0
#define OW2_S0 2816
#define OW3_S0 4096
#define OW1_S1 6656
#define OW2_S1 12288
#define OW3_S1 16896
#define OW1_S2 26112
#define OW2_S2 31744
#define OW3_S2 38656

// =====================================================================
// prep kernels
// =====================================================================
__global__ __launch_bounds__(512) void prep_pts_kernel(const float* __restrict__ pts)
{
    int i = blockIdx.x * 512 + threadIdx.x;
    float4 v = reinterpret_cast<const float4*>(pts)[i];
    __half2* o = reinterpret_cast<__half2*>(g_pts_h + (size_t)i * 4);
    o[0] = __floats2half2_rn(v.x, v.y);
    o[1] = __floats2half2_rn(v.z, v.w);
}

struct WPrep {
    const float* src[9];
    int dst[9], kuse[9], nc[9], kh[9];
};

__global__ __launch_bounds__(256) void prep_w_kernel(WPrep p)
{
    int stride = gridDim.x * 256;
    for (int m = 0; m < 9; m++) {
        int nc = p.nc[m], kh = p.kh[m], ku = p.kuse[m], dst = p.dst[m];
        const float* src = p.src[m];
        for (int t = blockIdx.x * 256 + threadIdx.x; t < nc * kh; t += stride) {
            int n = t / kh, k = t - n * kh;
            g_w_h[dst + t] = (k < ku) ? __float2half(src[k * nc + n]) : __half(0.0f);
        }
    }
}

// =====================================================================
// FPS
// =====================================================================
__global__ __launch_bounds__(256) void fps_kernel(const float* __restrict__ xyz,
                                                  float* __restrict__ out_newxyz)
{
    int b = blockIdx.x;
    extern __shared__ float sm[];
    float* sx = sm;
    float* sy = sm + NPTS;
    float* sz = sm + 2 * NPTS;
    __shared__ unsigned long long skey[3];

    const float* base = xyz + (size_t)b * NPTS * 3;
    float px[16], py[16], pz[16], pd[16];
    #pragma unroll
    for (int r = 0; r < 16; r++) {
        int p = threadIdx.x + r * 256;
        float x = base[p * 3 + 0];
        float y = base[p * 3 + 1];
        float z = base[p * 3 + 2];
        sx[p] = x; sy[p] = y; sz[p] = z;
        px[r] = x; py[r] = y; pz[r] = z;
        pd[r] = 1e10f;
    }
    if (threadIdx.x == 0) {
        skey[0] = 0xFFFFFFFFull;
        skey[1] = 0ull;
        skey[2] = 0ull;
    }
    __syncthreads();

    int lane = threadIdx.x & 31;

    for (int it = 0; it < NPOINT; it++) {
        int cur = it % 3, nxt = (it + 1) % 3, rst = (it + 2) % 3;
        unsigned int low = (unsigned int)skey[cur];
        int far = (int)(0xFFFFFFFFu - low);

        if (threadIdx.x == 0) {
            float fx = sx[far], fy = sy[far], fz = sz[far];
            int row = b * NPOINT + it;
            out_newxyz[row * 3 + 0] = fx;
            out_newxyz[row * 3 + 1] = fy;
            out_newxyz[row * 3 + 2] = fz;
            g_new_xyz[row * 3 + 0] = fx;
            g_new_xyz[row * 3 + 1] = fy;
            g_new_xyz[row * 3 + 2] = fz;
            skey[rst] = 0ull;
        }
        float cx = sx[far], cy = sy[far], cz = sz[far];

        float bv = -1.0f;
        int   bi = 0;
        #pragma unroll
        for (int r = 0; r < 16; r++) {
            float dx = px[r] - cx;
            float dy = py[r] - cy;
            float dz = pz[r] - cz;
            float d = __fadd_rn(__fadd_rn(__fmul_rn(dx, dx), __fmul_rn(dy, dy)),
                                __fmul_rn(dz, dz));
            float nd = fminf(pd[r], d);
            pd[r] = nd;
            if (nd > bv) { bv = nd; bi = threadIdx.x + r * 256; }
        }
        #pragma unroll
        for (int off = 16; off >= 1; off >>= 1) {
            float ov = __shfl_down_sync(0xffffffffu, bv, off);
            int   oi = __shfl_down_sync(0xffffffffu, bi, off);
            if (ov > bv || (ov == bv && oi < bi)) { bv = ov; bi = oi; }
        }
        if (lane == 0) {
            unsigned long long key =
                ((unsigned long long)__float_as_uint(bv) << 32) |
                (unsigned long long)(0xFFFFFFFFu - (unsigned int)bi);
            atomicMax(&skey[nxt], key);
        }
        __syncthreads();
    }
}

// =====================================================================
// Fused ball query
// =====================================================================
__global__ __launch_bounds__(256) void bq_fused_kernel(const float* __restrict__ xyz,
                                                       int* __restrict__ o0,
                                                       int* __restrict__ o1,
                                                       int* __restrict__ o2)
{
    extern __shared__ float sm[];
    float* sx = sm;
    float* sy = sm + NPTS;
    float* sz = sm + 2 * NPTS;

    int wid  = threadIdx.x >> 5;
    int lane = threadIdx.x & 31;
    int gw   = blockIdx.x * 8 + wid;
    int b    = gw >> 10;

    const float* base = xyz + (size_t)b * NPTS * 3;
    for (int t = threadIdx.x; t < NPTS * 3; t += 256) {
        int p = t / 3, c = t - p * 3;
        float v = base[t];
        (c == 0 ? sx : (c == 1 ? sy : sz))[p] = v;
    }
    __syncthreads();

    const float r2_0 = (float)(0.1 * 0.1);
    const float r2_1 = (float)(0.2 * 0.2);
    const float r2_2 = (float)(0.4 * 0.4);

    float cx = g_new_xyz[gw * 3 + 0];
    float cy = g_new_xyz[gw * 3 + 1];
    float cz = g_new_xyz[gw * 3 + 2];

    int* p0 = o0 + (size_t)gw * 16;
    int* p1 = o1 + (size_t)gw * 32;
    int* p2 = o2 + (size_t)gw * 128;

    int c0 = 0, c1 = 0, c2 = 0;
    int f0 = -1, f1 = -1, f2 = -1;
    unsigned lmask = (1u << lane) - 1u;

    for (int s = 0; s < NPTS; s += 32) {
        int p = s + lane;
        float dx = sx[p] - cx;
        float dy = sy[p] - cy;
        float dz = sz[p] - cz;
        float d2 = __fadd_rn(__fadd_rn(__fmul_rn(dx, dx), __fmul_rn(dy, dy)),
                             __fmul_rn(dz, dz));
        bool h0 = d2 < r2_0, h1 = d2 < r2_1, h2 = d2 < r2_2;
        unsigned m0 = __ballot_sync(0xffffffffu, h0);
        unsigned m1 = __ballot_sync(0xffffffffu, h1);
        unsigned m2 = __ballot_sync(0xffffffffu, h2);
        if (m0) {
            if (f0 < 0) f0 = s + (__ffs(m0) - 1);
            if (h0) { int pos = c0 + __popc(m0 & lmask); if (pos < 16) p0[pos] = p; }
            c0 += __popc(m0);
        }
        if (m1) {
            if (f1 < 0) f1 = s + (__ffs(m1) - 1);
            if (h1) { int pos = c1 + __popc(m1 & lmask); if (pos < 32) p1[pos] = p; }
            c1 += __popc(m1);
        }
        if (m2) {
            if (f2 < 0) f2 = s + (__ffs(m2) - 1);
            if (h2) { int pos = c2 + __popc(m2 & lmask); if (pos < 128) p2[pos] = p; }
            c2 += __popc(m2);
        }
        if (c0 >= 16 && c1 >= 32 && c2 >= 128) break;
    }
    for (int pos = c0 + lane; pos < 16; pos += 32) p0[pos] = f0;
    for (int pos = c1 + lane; pos < 32; pos += 32) p1[pos] = f1;
    for (int pos = c2 + lane; pos < 128; pos += 32) p2[pos] = f2;
}

// =====================================================================
// fp16 m16n8k16 mma pipeline with ldmatrix operand loads.
// =====================================================================
__device__ __forceinline__ void mma_f16(float* d, const uint32_t* a, const uint32_t* b) {
    asm volatile("mma.sync.aligned.m16n8k16.row.col.f32.f16.f16.f32 "
                 "{%0,%1,%2,%3},{%4,%5,%6,%7},{%8,%9},{%0,%1,%2,%3};"
                 : "+f"(d[0]), "+f"(d[1]), "+f"(d[2]), "+f"(d[3])
                 : "r"(a[0]), "r"(a[1]), "r"(a[2]), "r"(a[3]),
                   "r"(b[0]), "r"(b[1]));
}

__device__ __forceinline__ void ldsm_x4(uint32_t* r, uint32_t addr) {
    asm volatile("ldmatrix.sync.aligned.m8n8.x4.shared.b16 {%0,%1,%2,%3}, [%4];"
                 : "=r"(r[0]), "=r"(r[1]), "=r"(r[2]), "=r"(r[3]) : "r"(addr));
}
__device__ __forceinline__ void ldsm_x2(uint32_t* r, uint32_t addr) {
    asm volatile("ldmatrix.sync.aligned.m8n8.x2.shared.b16 {%0,%1}, [%2];"
                 : "=r"(r[0]), "=r"(r[1]) : "r"(addr));
}

__device__ __forceinline__ uint32_t smem_u32(const void* p) {
    return (uint32_t)__cvta_generic_to_shared(p);
}

template<int KSTEPS, int SA, int KH, int NT>
__device__ __forceinline__ void mma_accum(const __half* __restrict__ sA, int kOff,
                                          const __half* __restrict__ sW,
                                          float (&acc)[2][NT][4])
{
    int lane = threadIdx.x & 31;
    int w    = threadIdx.x >> 5;
    int m0   = (w >> 2) * 32;
    int n0   = (w & 3) * (NT * 8);

    int aRow = m0 + (lane & 7) + ((lane >> 3) & 1) * 8;
    int aCol = (lane >> 4) * 8;
    int bRowX4 = (lane & 7) + (lane >> 4) * 8;
    int bColX4 = ((lane >> 3) & 1) * 8;
    int bRowX2 = (lane & 7);
    int bColX2 = ((lane >> 3) & 1) * 8;

    for (int ks = 0; ks < KSTEPS; ks++) {
        int k0 = kOff + ks * 16;
        uint32_t a[2][4];
        #pragma unroll
        for (int mt = 0; mt < 2; mt++)
            ldsm_x4(a[mt], smem_u32(sA + (aRow + 16 * mt) * SA + aCol + k0));

        uint32_t bfr[NT][2];
        #pragma unroll
        for (int nt = 0; nt < NT; nt += 2) {
            if (nt + 1 < NT) {
                uint32_t tmp[4];
                ldsm_x4(tmp, smem_u32(sW + (n0 + 8 * nt + bRowX4) * KH + bColX4 + k0));
                bfr[nt][0] = tmp[0]; bfr[nt][1] = tmp[1];
                bfr[nt + 1][0] = tmp[2]; bfr[nt + 1][1] = tmp[3];
            } else {
                ldsm_x2(bfr[nt], smem_u32(sW + (n0 + 8 * nt + bRowX2) * KH + bColX2 + k0));
            }
        }
        #pragma unroll
        for (int nt = 0; nt < NT; nt++) {
            mma_f16(acc[0][nt], a[0], bfr[nt]);
            mma_f16(acc[1][nt], a[1], bfr[nt]);
        }
    }
}

template<int NT, int SOUT>
__device__ __forceinline__ void epi_relu(float (&acc)[2][NT][4],
                                         const float* __restrict__ gBias,
                                         __half* __restrict__ sOut)
{
    int lane = threadIdx.x & 31;
    int w    = threadIdx.x >> 5;
    int g    = lane >> 2;
    int tg   = lane & 3;
    int m0   = (w >> 2) * 32;
    int n0   = (w & 3) * (NT * 8);
    #pragma unroll
    for (int mt = 0; mt < 2; mt++)
        #pragma unroll
        for (int nt = 0; nt < NT; nt++) {
            int row = m0 + 16 * mt + g;
            int col = n0 + 8 * nt + 2 * tg;
            float b0v = gBias[col], b1v = gBias[col + 1];
            sOut[row * SOUT + col]           = __float2half(fmaxf(acc[mt][nt][0] + b0v, 0.0f));
            sOut[row * SOUT + col + 1]       = __float2half(fmaxf(acc[mt][nt][1] + b1v, 0.0f));
            sOut[(row + 8) * SOUT + col]     = __float2half(fmaxf(acc[mt][nt][2] + b0v, 0.0f));
            sOut[(row + 8) * SOUT + col + 1] = __float2half(fmaxf(acc[mt][nt][3] + b1v, 0.0f));
        }
}

template<int NT, int SEG>
__device__ __forceinline__ void epi_final(float (&acc)[2][NT][4],
                                          const float* __restrict__ gBias,
                                          int* __restrict__ sMaxI,
                                          float* __restrict__ outF, int centerBase)
{
    int lane = threadIdx.x & 31;
    int w    = threadIdx.x >> 5;
    int g    = lane >> 2;
    int tg   = lane & 3;
    int n0   = (w & 3) * (NT * 8);

    if (SEG == 128) {
        #pragma unroll
        for (int nt = 0; nt < NT; nt++) {
            int col = n0 + 8 * nt + 2 * tg;
            float v0 = fmaxf(fmaxf(acc[0][nt][0], acc[0][nt][2]),
                             fmaxf(acc[1][nt][0], acc[1][nt][2]));
            float v1 = fmaxf(fmaxf(acc[0][nt][1], acc[0][nt][3]),
                             fmaxf(acc[1][nt][1], acc[1][nt][3]));
            v0 = fmaxf(v0 + gBias[col], 0.0f);
            v1 = fmaxf(v1 + gBias[col + 1], 0.0f);
            #pragma unroll
            for (int off = 4; off < 32; off <<= 1) {
                v0 = fmaxf(v0, __shfl_xor_sync(0xffffffffu, v0, off));
                v1 = fmaxf(v1, __shfl_xor_sync(0xffffffffu, v1, off));
            }
            if (g == 0) {
                atomicMax(&sMaxI[col],     __float_as_int(v0));
                atomicMax(&sMaxI[col + 1], __float_as_int(v1));
            }
        }
    } else if (SEG == 32) {
        int center = centerBase + (w >> 2);
        #pragma unroll
        for (int nt = 0; nt < NT; nt++) {
            int col = n0 + 8 * nt + 2 * tg;
            float v0 = fmaxf(fmaxf(acc[0][nt][0], acc[0][nt][2]),
                             fmaxf(acc[1][nt][0], acc[1][nt][2]));
            float v1 = fmaxf(fmaxf(acc[0][nt][1], acc[0][nt][3]),
                             fmaxf(acc[1][nt][1], acc[1][nt][3]));
            #pragma unroll
            for (int off = 4; off < 32; off <<= 1) {
                v0 = fmaxf(v0, __shfl_xor_sync(0xffffffffu, v0, off));
                v1 = fmaxf(v1, __shfl_xor_sync(0xffffffffu, v1, off));
            }
            if (g == 0) {
                float* op = outF + (size_t)center * FEAT_W;
                op[col]     = fmaxf(v0 + gBias[col], 0.0f);
                op[col + 1] = fmaxf(v1 + gBias[col + 1], 0.0f);
            }
        }
    } else { // SEG == 16
        #pragma unroll
        for (int mt = 0; mt < 2; mt++) {
            int center = centerBase + (w >> 2) * 2 + mt;
            #pragma unroll
            for (int nt = 0; nt < NT; nt++) {
                int col = n0 + 8 * nt + 2 * tg;
                float v0 = fmaxf(acc[mt][nt][0], acc[mt][nt][2]);
                float v1 = fmaxf(acc[mt][nt][1], acc[mt][nt][3]);
                #pragma unroll
                for (int off = 4; off < 32; off <<= 1) {
                    v0 = fmaxf(v0, __shfl_xor_sync(0xffffffffu, v0, off));
                    v1 = fmaxf(v1, __shfl_xor_sync(0xffffffffu, v1, off));
                }
                if (g == 0) {
                    float* op = outF + (size_t)center * FEAT_W;
                    op[col]     = fmaxf(v0 + gBias[col], 0.0f);
                    op[col + 1] = fmaxf(v1 + gBias[col + 1], 0.0f);
                }
            }
        }
    }
}

template<int NHALVES>
__device__ __forceinline__ void stage_copy(__half* __restrict__ sW,
                                           const __half* __restrict__ gW)
{
    static_assert(NHALVES % 8 == 0, "16B granularity");
    for (int t = threadIdx.x; t < NHALVES / 8; t += NTH)
        reinterpret_cast<uint4*>(sW)[t] = reinterpret_cast<const uint4*>(gW)[t];
}

// =====================================================================
// Persistent MLP kernel: weights staged ONCE per block, loop over tiles.
// One tile = 128 rows = (128/SEG) centers.
// =====================================================================
template<int SEG, int C1, int C2, int C3, int OW1, int OW2, int OW3>
__global__ __launch_bounds__(NTH, 2) void mlp_mma_kernel(
    const float* __restrict__ xyz,
    const int* __restrict__ idxbuf,
    const float* __restrict__ B1,
    const float* __restrict__ B2,
    const float* __restrict__ B3,
    float* __restrict__ outF)
{
    constexpr int CPB  = 128 / SEG;
    constexpr int NTILES = NCENT / CPB;
    constexpr int S1   = SHPAD(C1);
    constexpr int S2   = SHPAD(C2);
    constexpr int KH1  = SH_IN;
    constexpr int KH2  = SHPAD(C1);
    constexpr int KH3  = SHPAD(C2);
    constexpr int REG0 = 128 * cmax2i(SH_IN, S2);
    constexpr int NW1  = C1 * KH1, NW2 = C2 * KH2, NW3 = C3 * KH3;
    constexpr int NT1  = C1 / 32, NT2 = C2 / 32, NT3 = C3 / 32;
    constexpr int KS2  = C1 / 16, KS3 = C2 / 16;

    extern __shared__ __half smh[];
    __half* sIn   = smh;                    // [REG0] (also buf2)
    __half* buf1  = smh + REG0;             // 128 * S1
    __half* sW1   = buf1 + 128 * S1;        // NW1
    __half* sW2   = sW1 + NW1;              // NW2
    __half* sW3   = sW2 + NW2;              // NW3
    int*    sMaxI = (int*)(sW3 + NW3);      // 128
    int*    sIdx  = sMaxI + 128;            // 128

    // stage all weights once
    stage_copy<NW1>(sW1, g_w_h + OW1);
    stage_copy<NW2>(sW2, g_w_h + OW2);
    stage_copy<NW3>(sW3, g_w_h + OW3);
    __syncthreads();

    for (int tile = blockIdx.x; tile < NTILES; tile += gridDim.x) {
        int centerBase = tile * CPB;
        int b = centerBase >> 10;

        for (int t = threadIdx.x; t < 128; t += NTH) {
            sIdx[t]  = idxbuf[(size_t)centerBase * SEG + t];
            sMaxI[t] = 0;
        }
        __syncthreads();

        const __half* pH = g_pts_h + (size_t)b * NPTS * CIN_PTS;
        const float*  xB = xyz + (size_t)b * NPTS * 3;

        for (int t = threadIdx.x; t < 128 * 8; t += NTH) {
            int s = t >> 3, c = t & 7;
            uint4 v = *reinterpret_cast<const uint4*>(pH + (size_t)sIdx[s] * CIN_PTS + c * 8);
            *reinterpret_cast<uint4*>(sIn + s * SH_IN + c * 8) = v;
        }
        for (int t = threadIdx.x; t < 128 * 16; t += NTH) {
            int s = t >> 4, c = 64 + (t & 15);
            __half v = __half(0.0f);
            if (c < 67) {
                int d = c - 64;
                int ci = centerBase + s / SEG;
                v = __float2half(xB[(size_t)sIdx[s] * 3 + d] - g_new_xyz[ci * 3 + d]);
            }
            sIn[s * SH_IN + c] = v;
        }
        __syncthreads();

        // layer 1: sIn -> buf1
        {
            float acc[2][NT1][4];
            #pragma unroll
            for (int mt = 0; mt < 2; mt++)
                #pragma unroll
                for (int nt = 0; nt < NT1; nt++)
                    #pragma unroll
                    for (int i = 0; i < 4; i++) acc[mt][nt][i] = 0.0f;
            mma_accum<5, SH_IN, KH1, NT1>(sIn, 0, sW1, acc);
            epi_relu<NT1, S1>(acc, B1, buf1);
        }
        __syncthreads();

        // layer 2: buf1 -> buf2 (aliases sIn; all L1 reads done at sync)
        __half* buf2 = sIn;
        {
            float acc[2][NT2][4];
            #pragma unroll
            for (int mt = 0; mt < 2; mt++)
                #pragma unroll
                for (int nt = 0; nt < NT2; nt++)
                    #pragma unroll
                    for (int i = 0; i < 4; i++) acc[mt][nt][i] = 0.0f;
            mma_accum<KS2, S1, KH2, NT2>(buf1, 0, sW2, acc);
            epi_relu<NT2, S2>(acc, B2, buf2);
        }
        __syncthreads();

        // layer 3: buf2 -> maxpool output
        {
            float acc[2][NT3][4];
            #pragma unroll
            for (int mt = 0; mt < 2; mt++)
                #pragma unroll
                for (int nt = 0; nt < NT3; nt++)
                    #pragma unroll
                    for (int i = 0; i < 4; i++) acc[mt][nt][i] = 0.0f;
            mma_accum<KS3, S2, KH3, NT3>(buf2, 0, sW3, acc);
            epi_final<NT3, SEG>(acc, B3, sMaxI, outF, centerBase);
        }

        if (SEG == 128) {
            __syncthreads();
            for (int t = threadIdx.x; t < C3; t += NTH)
                outF[(size_t)centerBase * FEAT_W + t] = __int_as_float(sMaxI[t]);
        }
        __syncthreads();   // protect sIn/buf2 + sMaxI before next tile
    }
}

// =====================================================================
// host launch
// =====================================================================
template<int SEG, int C1, int C2, int C3>
static constexpr int smem_mma() {
    constexpr int REG0 = 128 * cmax2i(SH_IN, SHPAD(C2));
    constexpr int NW = C1 * SH_IN + C2 * SHPAD(C1) + C3 * SHPAD(C2);
    return (REG0 + 128 * SHPAD(C1) + NW) * 2 + 256 * 4;
}

extern "C" void kernel_launch(void* const* d_in, const int* in_sizes, int n_in,
                              void* d_out, int out_size)
{
    const float* xyz = (const float*)d_in[0];
    const float* pts = (const float*)d_in[1];
    const float* W[3][3];
    const float* Bv[3][3];
    int k = 2;
    for (int bi = 0; bi < 3; bi++)
        for (int li = 0; li < 3; li++) {
            W[bi][li]  = (const float*)d_in[k++];
            Bv[bi][li] = (const float*)d_in[k++];
        }

    float* out        = (float*)d_out;
    float* out_newxyz = out;
    float* out_feat   = out + (size_t)NCENT * 3;

    const int fps_smem = 3 * NPTS * 4;
    const int bq_smem  = 3 * NPTS * 4;
    constexpr int sm0 = smem_mma<16, 32, 32, 64>();     //  47,104 B
    constexpr int sm1 = smem_mma<32, 64, 64, 128>();    //  80,896 B -> 2/SM
    constexpr int sm2 = smem_mma<128, 64, 96, 128>();   //  97,792 B -> 2/SM

    cudaFuncSetAttribute(fps_kernel, cudaFuncAttributeMaxDynamicSharedMemorySize, fps_smem);
    cudaFuncSetAttribute((const void*)mlp_mma_kernel<16, 32, 32, 64, OW1_S0, OW2_S0, OW3_S0>,
                         cudaFuncAttributeMaxDynamicSharedMemorySize, sm0);
    cudaFuncSetAttribute((const void*)mlp_mma_kernel<32, 64, 64, 128, OW1_S1, OW2_S1, OW3_S1>,
                         cudaFuncAttributeMaxDynamicSharedMemorySize, sm1);
    cudaFuncSetAttribute((const void*)mlp_mma_kernel<128, 64, 96, 128, OW1_S2, OW2_S2, OW3_S2>,
                         cudaFuncAttributeMaxDynamicSharedMemorySize, sm2);

    // prep: fp16 points + padded transposed fp16 weights
    prep_pts_kernel<<<(BATCH * NPTS * CIN_PTS / 4) / 512, 512>>>(pts);
    WPrep wp;
    const float* srcs[9] = { W[0][0], W[0][1], W[0][2],
                             W[1][0], W[1][1], W[1][2],
                             W[2][0], W[2][1], W[2][2] };
    int dsts[9] = { OW1_S0, OW2_S0, OW3_S0, OW1_S1, OW2_S1, OW3_S1, OW1_S2, OW2_S2, OW3_S2 };
    int kus[9]  = { 67, 32, 32, 67, 64, 64, 67, 64, 96 };
    int ncs[9]  = { 32, 32, 64, 64, 64, 128, 64, 96, 128 };
    int khs[9]  = { 88, 40, 40, 88, 72, 72, 88, 72, 104 };
    for (int i = 0; i < 9; i++) {
        wp.src[i] = srcs[i]; wp.dst[i] = dsts[i];
        wp.kuse[i] = kus[i]; wp.nc[i] = ncs[i]; wp.kh[i] = khs[i];
    }
    prep_w_kernel<<<64, 256>>>(wp);

    fps_kernel<<<BATCH, 256, fps_smem>>>(xyz, out_newxyz);
    bq_fused_kernel<<<NCENT / 8, 256, bq_smem>>>(xyz, g_idx0, g_idx1, g_idx2);

    mlp_mma_kernel<128, 64, 96, 128, OW1_S2, OW2_S2, OW3_S2><<<PGRID, NTH, sm2>>>(
        xyz, g_idx2, Bv[2][0], Bv[2][1], Bv[2][2], out_feat + 192);
    mlp_mma_kernel<32, 64, 64, 128, OW1_S1, OW2_S1, OW3_S1><<<PGRID, NTH, sm1>>>(
        xyz, g_idx1, Bv[1][0], Bv[1][1], Bv[1][2], out_feat + 64);
    mlp_mma_kernel<16, 32, 32, 64, OW1_S0, OW2_S0, OW3_S0><<<PGRID, NTH, sm0>>>(
        xyz, g_idx0, Bv[0][0], Bv[0][1], Bv[0][2], out_feat + 0);
}